// round 1
// baseline (speedup 1.0000x reference)
#include <cuda_runtime.h>
#include <math.h>

#define D_DIM 768
#define T_MAX 8192
#define PITCH 772          // floats; 772 % 32 == 4 -> conflict-free row access patterns
#define NT 256

// Scratch for precomputed Q = E @ Wq^T + bq  (25.2 MB, fits easily; static __device__ per rules)
__device__ float g_Q[(size_t)T_MAX * D_DIM];

// ---------------------------------------------------------------------------
// Kernel 1: Q[t, e] = sum_d E[t, d] * Wq[e, d] + bq[e]     (NT GEMM, fp32)
// BM=128, BN=64, BK=16, 256 threads, 8x4 microtile per thread.
// ---------------------------------------------------------------------------
__global__ __launch_bounds__(256) void qproj_kernel(
    const float* __restrict__ E, const float* __restrict__ Wq,
    const float* __restrict__ bq, int T)
{
    const int BM = 128, BN = 64, BK = 16;
    __shared__ float As[BK][BM + 4];
    __shared__ float Bs[BK][BN + 4];

    const int tid = threadIdx.x;
    const int mbase = blockIdx.y * BM;
    const int nbase = blockIdx.x * BN;
    const int ty = tid >> 4;   // 0..15 : rows ty + 16*i
    const int tx = tid & 15;   // 0..15 : cols tx + 16*j

    float acc[8][4];
#pragma unroll
    for (int i = 0; i < 8; i++)
#pragma unroll
        for (int j = 0; j < 4; j++) acc[i][j] = 0.f;

    for (int k0 = 0; k0 < D_DIM; k0 += BK) {
        // Load A tile (128 rows x 16 k) : 512 float4, 2 per thread, coalesced
#pragma unroll
        for (int u = 0; u < 2; u++) {
            int idx = u * 256 + tid;
            int r = idx >> 2;
            int c4 = (idx & 3) * 4;
            int row = mbase + r;
            float4 v = make_float4(0.f, 0.f, 0.f, 0.f);
            if (row < T)
                v = *reinterpret_cast<const float4*>(&E[(size_t)row * D_DIM + k0 + c4]);
            As[c4 + 0][r] = v.x; As[c4 + 1][r] = v.y;
            As[c4 + 2][r] = v.z; As[c4 + 3][r] = v.w;
        }
        // Load B tile (64 rows x 16 k) : 256 float4, 1 per thread
        {
            int r = tid >> 2;
            int c4 = (tid & 3) * 4;
            float4 v = *reinterpret_cast<const float4*>(
                &Wq[(size_t)(nbase + r) * D_DIM + k0 + c4]);
            Bs[c4 + 0][r] = v.x; Bs[c4 + 1][r] = v.y;
            Bs[c4 + 2][r] = v.z; Bs[c4 + 3][r] = v.w;
        }
        __syncthreads();

#pragma unroll
        for (int kk = 0; kk < BK; kk++) {
            float a[8], b[4];
#pragma unroll
            for (int i = 0; i < 8; i++) a[i] = As[kk][ty + 16 * i];
#pragma unroll
            for (int j = 0; j < 4; j++) b[j] = Bs[kk][tx + 16 * j];
#pragma unroll
            for (int i = 0; i < 8; i++)
#pragma unroll
                for (int j = 0; j < 4; j++) acc[i][j] += a[i] * b[j];
        }
        __syncthreads();
    }

#pragma unroll
    for (int j = 0; j < 4; j++) {
        float bv = bq[nbase + tx + 16 * j];
#pragma unroll
        for (int i = 0; i < 8; i++) {
            int row = mbase + ty + 16 * i;
            if (row < T)
                g_Q[(size_t)row * D_DIM + nbase + tx + 16 * j] = acc[i][j] + bv;
        }
    }
}

// ---------------------------------------------------------------------------
// Kernel 2: one CTA per span.
// Scores S = Qspan @ Espan^T via 4-way D-split (groups of 64 threads, 4x4
// microtile over an (8*NB)x(8*NB) score tile), partial-sum reduction, warp
// softmax over k (len<=32 fits one warp), column-sum, then out = csum @ Espan.
// ---------------------------------------------------------------------------

template<int NB>
__device__ __forceinline__ void scores_compute(
    const float* __restrict__ Qs, const float* __restrict__ Es,
    float* __restrict__ Sb, int tid)
{
    const int g  = tid >> 6;       // 0..3  : D slice [g*192, g*192+192)
    const int s  = tid & 63;
    const int sy = s >> 3;         // 0..7  : rows  sy + 8*i
    const int sx = s & 7;          // 0..7  : cols  sx + 8*j

    const float* qb = Qs + g * 192 + sy * PITCH;
    const float* eb = Es + g * 192 + sx * PITCH;

    float acc[NB][NB];
#pragma unroll
    for (int i = 0; i < NB; i++)
#pragma unroll
        for (int j = 0; j < NB; j++) acc[i][j] = 0.f;

#pragma unroll 4
    for (int kk = 0; kk < 192; kk++) {
        float a[NB], b[NB];
#pragma unroll
        for (int i = 0; i < NB; i++) a[i] = qb[i * 8 * PITCH + kk];
#pragma unroll
        for (int j = 0; j < NB; j++) b[j] = eb[j * 8 * PITCH + kk];
#pragma unroll
        for (int i = 0; i < NB; i++)
#pragma unroll
            for (int j = 0; j < NB; j++) acc[i][j] += a[i] * b[j];
    }

    float* dst = Sb + g * 1056 + sy * 33 + sx;
#pragma unroll
    for (int i = 0; i < NB; i++)
#pragma unroll
        for (int j = 0; j < NB; j++)
            dst[i * 8 * 33 + j * 8] = acc[i][j];
}

__global__ __launch_bounds__(256) void span_kernel(
    const float* __restrict__ E, const int* __restrict__ spans,
    float* __restrict__ out)
{
    extern __shared__ float sm[];
    float* Qs   = sm;                       // 32 * 772
    float* Es   = Qs + 32 * PITCH;          // 32 * 772
    float* Sb   = Es + 32 * PITCH;          // 4 * 32 * 33 partials
    float* S    = Sb + 4 * 1056;            // 32 * 33 final scores/weights
    float* csum = S + 1056;                 // 32

    const int n = blockIdx.x;
    const int tid = threadIdx.x;
    const int start = spans[2 * n];
    const int len   = spans[2 * n + 1] - start + 1;   // 1..32
    const int nb    = (len + 7) >> 3;                 // 1..4

    // ---- Phase A: stage Q and E rows of the span into shared (float4) ----
    const int tot4 = len * (D_DIM / 4);
    for (int idx = tid; idx < tot4; idx += NT) {
        int r = idx / (D_DIM / 4);
        int c = (idx % (D_DIM / 4)) * 4;
        size_t goff = (size_t)(start + r) * D_DIM + c;
        *reinterpret_cast<float4*>(&Qs[r * PITCH + c]) =
            *reinterpret_cast<const float4*>(&g_Q[goff]);
        *reinterpret_cast<float4*>(&Es[r * PITCH + c]) =
            *reinterpret_cast<const float4*>(&E[goff]);
    }
    __syncthreads();

    // ---- Phase B: scores (D-split partial GEMM) ----
    switch (nb) {
        case 1: scores_compute<1>(Qs, Es, Sb, tid); break;
        case 2: scores_compute<2>(Qs, Es, Sb, tid); break;
        case 3: scores_compute<3>(Qs, Es, Sb, tid); break;
        default: scores_compute<4>(Qs, Es, Sb, tid); break;
    }
    __syncthreads();

    // ---- Reduce 4 partials ----
    const int side = nb * 8;
    for (int idx = tid; idx < side * side; idx += NT) {
        int q = idx / side, k = idx % side;
        int o = q * 33 + k;
        S[o] = Sb[o] + Sb[1056 + o] + Sb[2112 + o] + Sb[3168 + o];
    }
    __syncthreads();

    // ---- Softmax over k (one warp per row; k fits in 32 lanes) ----
    const int warp = tid >> 5, lane = tid & 31;
#pragma unroll
    for (int r = 0; r < 4; r++) {
        int q = warp + 8 * r;
        if (q < len) {
            float x = (lane < len) ? S[q * 33 + lane] : -INFINITY;
            float m = x;
#pragma unroll
            for (int off = 16; off; off >>= 1)
                m = fmaxf(m, __shfl_xor_sync(0xffffffffu, m, off));
            float e = (lane < len) ? __expf(x - m) : 0.f;
            float ssum = e;
#pragma unroll
            for (int off = 16; off; off >>= 1)
                ssum += __shfl_xor_sync(0xffffffffu, ssum, off);
            S[q * 33 + lane] = e / ssum;
        }
    }
    __syncthreads();

    // ---- Column sums of weights over valid q ----
    if (tid < 32) {
        float c = 0.f;
        if (tid < len)
            for (int q = 0; q < len; q++) c += S[q * 33 + tid];
        csum[tid] = c;
    }
    __syncthreads();

    // ---- Output: out[n, d] = sum_k csum[k] * E[start + k, d] ----
    for (int d = tid; d < D_DIM; d += NT) {
        float a = 0.f;
        for (int k = 0; k < len; k++) a += csum[k] * Es[k * PITCH + d];
        out[(size_t)n * D_DIM + d] = a;
    }
}

// ---------------------------------------------------------------------------
// Launch
// ---------------------------------------------------------------------------
static const int SPAN_SMEM_BYTES =
    (2 * 32 * PITCH + 4 * 1056 + 1056 + 32) * (int)sizeof(float);   // 218880 B

extern "C" void kernel_launch(void* const* d_in, const int* in_sizes, int n_in,
                              void* d_out, int out_size)
{
    const float* E     = (const float*)d_in[0];
    const int*   spans = (const int*)d_in[1];
    const float* Wq    = (const float*)d_in[2];
    const float* bq    = (const float*)d_in[3];
    float*       out   = (float*)d_out;

    const int T = in_sizes[0] / D_DIM;
    const int N = in_sizes[1] / 2;

    dim3 g1(D_DIM / 64, (T + 127) / 128);
    qproj_kernel<<<g1, 256>>>(E, Wq, bq, T);

    cudaFuncSetAttribute(span_kernel,
                         cudaFuncAttributeMaxDynamicSharedMemorySize,
                         SPAN_SMEM_BYTES);
    span_kernel<<<N, 256, SPAN_SMEM_BYTES>>>(E, spans, out);
}

// round 3
// speedup vs baseline: 1.3364x; 1.3364x over previous
#include <cuda_runtime.h>
#include <math.h>

#define D_DIM 768
#define T_MAX 8192
#define NT 256
#define CHUNK 192
#define CP 196      // chunk pitch (floats): %32==4 -> conflict-free, %4==0 -> float4 ok
#define NCH 4       // D_DIM / CHUNK

// Precomputed Q = E @ Wq^T + bq  (25.2 MB scratch)
__device__ float g_Q[(size_t)T_MAX * D_DIM];

// ---------------------------------------------------------------------------
// Kernel 1: Q[t, e] = sum_d E[t, d] * Wq[e, d] + bq[e]     (NT GEMM, fp32)
// ---------------------------------------------------------------------------
__global__ __launch_bounds__(256) void qproj_kernel(
    const float* __restrict__ E, const float* __restrict__ Wq,
    const float* __restrict__ bq, int T)
{
    const int BM = 128, BN = 64, BK = 16;
    __shared__ float As[BK][BM + 4];
    __shared__ float Bs[BK][BN + 4];

    const int tid = threadIdx.x;
    const int mbase = blockIdx.y * BM;
    const int nbase = blockIdx.x * BN;
    const int ty = tid >> 4;
    const int tx = tid & 15;

    float acc[8][4];
#pragma unroll
    for (int i = 0; i < 8; i++)
#pragma unroll
        for (int j = 0; j < 4; j++) acc[i][j] = 0.f;

    for (int k0 = 0; k0 < D_DIM; k0 += BK) {
#pragma unroll
        for (int u = 0; u < 2; u++) {
            int idx = u * 256 + tid;
            int r = idx >> 2;
            int c4 = (idx & 3) * 4;
            int row = mbase + r;
            float4 v = make_float4(0.f, 0.f, 0.f, 0.f);
            if (row < T)
                v = *reinterpret_cast<const float4*>(&E[(size_t)row * D_DIM + k0 + c4]);
            As[c4 + 0][r] = v.x; As[c4 + 1][r] = v.y;
            As[c4 + 2][r] = v.z; As[c4 + 3][r] = v.w;
        }
        {
            int r = tid >> 2;
            int c4 = (tid & 3) * 4;
            float4 v = *reinterpret_cast<const float4*>(
                &Wq[(size_t)(nbase + r) * D_DIM + k0 + c4]);
            Bs[c4 + 0][r] = v.x; Bs[c4 + 1][r] = v.y;
            Bs[c4 + 2][r] = v.z; Bs[c4 + 3][r] = v.w;
        }
        __syncthreads();

#pragma unroll
        for (int kk = 0; kk < BK; kk++) {
            float a[8], b[4];
#pragma unroll
            for (int i = 0; i < 8; i++) a[i] = As[kk][ty + 16 * i];
#pragma unroll
            for (int j = 0; j < 4; j++) b[j] = Bs[kk][tx + 16 * j];
#pragma unroll
            for (int i = 0; i < 8; i++)
#pragma unroll
                for (int j = 0; j < 4; j++) acc[i][j] += a[i] * b[j];
        }
        __syncthreads();
    }

#pragma unroll
    for (int j = 0; j < 4; j++) {
        float bv = bq[nbase + tx + 16 * j];
#pragma unroll
        for (int i = 0; i < 8; i++) {
            int row = mbase + ty + 16 * i;
            if (row < T)
                g_Q[(size_t)row * D_DIM + nbase + tx + 16 * j] = acc[i][j] + bv;
        }
    }
}

// ---------------------------------------------------------------------------
// Kernel 2: one CTA per span, D chunked into 4x192 slices, score partials in
// registers across chunks, LDS.128-vectorized score GEMM (8 FMA / LDS instr).
// ---------------------------------------------------------------------------

template<int NB>
__device__ __forceinline__ void scores_chunk(
    const float* __restrict__ Qc, const float* __restrict__ Ec,
    float (&acc)[NB][NB], int g, int sy, int sx)
{
    // group g covers chunk columns [g*48, g*48+48) -> 12 float4 steps
    const float4* qb = reinterpret_cast<const float4*>(Qc + g * 48 + sy * CP);
    const float4* eb = reinterpret_cast<const float4*>(Ec + g * 48 + sx * CP);
#pragma unroll
    for (int kk = 0; kk < 12; kk++) {
        float4 a[NB];
#pragma unroll
        for (int i = 0; i < NB; i++) a[i] = qb[i * 8 * (CP / 4) + kk];
#pragma unroll
        for (int j = 0; j < NB; j++) {
            float4 b = eb[j * 8 * (CP / 4) + kk];
#pragma unroll
            for (int i = 0; i < NB; i++) {
                acc[i][j] += a[i].x * b.x;
                acc[i][j] += a[i].y * b.y;
                acc[i][j] += a[i].z * b.z;
                acc[i][j] += a[i].w * b.w;
            }
        }
    }
}

template<int NB>
__device__ __forceinline__ void span_scores(
    const float* __restrict__ E, float* Qc, float* Ec, float* Sb,
    int start, int len, int tid, int g, int sy, int sx)
{
    float acc[NB][NB];
#pragma unroll
    for (int i = 0; i < NB; i++)
#pragma unroll
        for (int j = 0; j < NB; j++) acc[i][j] = 0.f;

    const int tot4 = len * (CHUNK / 4);
    for (int c = 0; c < NCH; c++) {
        // stage this D-chunk of Q and E (float4, coalesced)
        for (int idx = tid; idx < tot4; idx += NT) {
            int r = idx / (CHUNK / 4);
            int q4 = idx - r * (CHUNK / 4);
            size_t goff = (size_t)(start + r) * D_DIM + c * CHUNK + q4 * 4;
            reinterpret_cast<float4*>(Qc)[r * (CP / 4) + q4] =
                *reinterpret_cast<const float4*>(&g_Q[goff]);
            reinterpret_cast<float4*>(Ec)[r * (CP / 4) + q4] =
                *reinterpret_cast<const float4*>(&E[goff]);
        }
        __syncthreads();
        scores_chunk<NB>(Qc, Ec, acc, g, sy, sx);
        __syncthreads();
    }

    float* dst = Sb + g * 1056 + sy * 33 + sx;
#pragma unroll
    for (int i = 0; i < NB; i++)
#pragma unroll
        for (int j = 0; j < NB; j++)
            dst[i * 8 * 33 + j * 8] = acc[i][j];
}

__global__ __launch_bounds__(256, 3) void span_kernel(
    const float* __restrict__ E, const int* __restrict__ spans,
    float* __restrict__ out)
{
    extern __shared__ float sm[];
    float* Qc   = sm;                      // 32 * 196
    float* Ec   = Qc + 32 * CP;            // 32 * 196
    float* Sb   = Ec + 32 * CP;            // 4 * 1056 partials
    float* S    = Sb + 4 * 1056;           // 32 * 33 scores/weights
    float* csum = S + 1056;                // 32

    const int n = blockIdx.x;
    const int tid = threadIdx.x;
    const int start = spans[2 * n];
    const int len   = spans[2 * n + 1] - start + 1;   // 1..32
    const int nb    = (len + 7) >> 3;                 // 1..4

    const int g  = tid >> 6;
    const int s  = tid & 63;
    const int sy = s >> 3;
    const int sx = s & 7;

    switch (nb) {
        case 1: span_scores<1>(E, Qc, Ec, Sb, start, len, tid, g, sy, sx); break;
        case 2: span_scores<2>(E, Qc, Ec, Sb, start, len, tid, g, sy, sx); break;
        case 3: span_scores<3>(E, Qc, Ec, Sb, start, len, tid, g, sy, sx); break;
        default: span_scores<4>(E, Qc, Ec, Sb, start, len, tid, g, sy, sx); break;
    }
    __syncthreads();

    // ---- Reduce 4 D-slice partials ----
    const int side = nb * 8;
    for (int idx = tid; idx < side * side; idx += NT) {
        int q = idx / side, k = idx - q * side;
        int o = q * 33 + k;
        S[o] = Sb[o] + Sb[1056 + o] + Sb[2112 + o] + Sb[3168 + o];
    }
    __syncthreads();

    // ---- Softmax over k (one warp per q-row) ----
    const int warp = tid >> 5, lane = tid & 31;
#pragma unroll
    for (int r = 0; r < 4; r++) {
        int q = warp + 8 * r;
        if (q < len) {
            float x = (lane < len) ? S[q * 33 + lane] : -INFINITY;
            float m = x;
#pragma unroll
            for (int off = 16; off; off >>= 1)
                m = fmaxf(m, __shfl_xor_sync(0xffffffffu, m, off));
            float e = (lane < len) ? __expf(x - m) : 0.f;
            float ssum = e;
#pragma unroll
            for (int off = 16; off; off >>= 1)
                ssum += __shfl_xor_sync(0xffffffffu, ssum, off);
            S[q * 33 + lane] = e / ssum;
        }
    }
    __syncthreads();

    // ---- Column sums of weights over valid q ----
    if (tid < 32) {
        float c = 0.f;
        if (tid < len)
            for (int q = 0; q < len; q++) c += S[q * 33 + tid];
        csum[tid] = c;
    }
    __syncthreads();

    // ---- Output: out[n, d] = sum_k csum[k] * E[start + k, d]  (E via L2) ----
    {
        const float* eb = E + (size_t)start * D_DIM + tid;
        float a0 = 0.f, a1 = 0.f, a2 = 0.f;
        for (int k = 0; k < len; k++) {
            float w = csum[k];
            const float* p = eb + (size_t)k * D_DIM;
            a0 += w * p[0];
            a1 += w * p[256];
            a2 += w * p[512];
        }
        float* op = out + (size_t)n * D_DIM + tid;
        op[0]   = a0;
        op[256] = a1;
        op[512] = a2;
    }
}

// ---------------------------------------------------------------------------
// Launch
// ---------------------------------------------------------------------------
static const int SPAN_SMEM_BYTES =
    (2 * 32 * CP + 4 * 1056 + 1056 + 32) * (int)sizeof(float);   // 71424 B

extern "C" void kernel_launch(void* const* d_in, const int* in_sizes, int n_in,
                              void* d_out, int out_size)
{
    const float* E     = (const float*)d_in[0];
    const int*   spans = (const int*)d_in[1];
    const float* Wq    = (const float*)d_in[2];
    const float* bq    = (const float*)d_in[3];
    float*       out   = (float*)d_out;

    const int T = in_sizes[0] / D_DIM;
    const int N = in_sizes[1] / 2;

    dim3 g1(D_DIM / 64, (T + 127) / 128);
    qproj_kernel<<<g1, 256>>>(E, Wq, bq, T);

    cudaFuncSetAttribute(span_kernel,
                         cudaFuncAttributeMaxDynamicSharedMemorySize,
                         SPAN_SMEM_BYTES);
    span_kernel<<<N, 256, SPAN_SMEM_BYTES>>>(E, spans, out);
}

// round 5
// speedup vs baseline: 1.8279x; 1.3677x over previous
#include <cuda_runtime.h>
#include <cuda_bf16.h>
#include <math.h>
#include <stdint.h>

#define D_DIM 768
#define T_MAX 8192
#define NT 256
#define CHUNK 192
#define CP 196
#define NCH 4

// Scratch (__device__ globals per harness rules)
__device__ float         g_Q[(size_t)T_MAX * D_DIM];
__device__ __nv_bfloat16 g_Ehi[(size_t)T_MAX * D_DIM];
__device__ __nv_bfloat16 g_Elo[(size_t)T_MAX * D_DIM];
__device__ __nv_bfloat16 g_Whi[(size_t)D_DIM * D_DIM];
__device__ __nv_bfloat16 g_Wlo[(size_t)D_DIM * D_DIM];

// ---------------------------------------------------------------------------
// Helpers (baseline PTX only — NO tcgen05, harness targets plain sm_103)
// ---------------------------------------------------------------------------
__device__ __forceinline__ uint32_t smem_u32(const void* p) {
    uint32_t a;
    asm("{ .reg .u64 t; cvta.to.shared.u64 t, %1; cvt.u32.u64 %0, t; }"
        : "=r"(a) : "l"(p));
    return a;
}

__device__ __forceinline__ void ldmx4(uint32_t* r, uint32_t addr) {
    asm volatile("ldmatrix.sync.aligned.m8n8.x4.shared.b16 {%0,%1,%2,%3}, [%4];"
                 : "=r"(r[0]), "=r"(r[1]), "=r"(r[2]), "=r"(r[3]) : "r"(addr));
}

__device__ __forceinline__ void mma16816(float* c, const uint32_t* a,
                                         const uint32_t* b) {
    asm volatile(
        "mma.sync.aligned.m16n8k16.row.col.f32.bf16.bf16.f32 "
        "{%0,%1,%2,%3}, {%4,%5,%6,%7}, {%8,%9}, {%0,%1,%2,%3};"
        : "+f"(c[0]), "+f"(c[1]), "+f"(c[2]), "+f"(c[3])
        : "r"(a[0]), "r"(a[1]), "r"(a[2]), "r"(a[3]), "r"(b[0]), "r"(b[1]));
}

// ---------------------------------------------------------------------------
// Kernel 0: fp32 -> (bf16 hi, bf16 lo) split
// ---------------------------------------------------------------------------
__global__ __launch_bounds__(256) void cvt_kernel(
    const float* __restrict__ src, __nv_bfloat16* __restrict__ hi,
    __nv_bfloat16* __restrict__ lo, int n4)
{
    int i = blockIdx.x * blockDim.x + threadIdx.x;
    if (i >= n4) return;
    float4 v = reinterpret_cast<const float4*>(src)[i];
    __nv_bfloat16 h0 = __float2bfloat16_rn(v.x);
    __nv_bfloat16 h1 = __float2bfloat16_rn(v.y);
    __nv_bfloat16 h2 = __float2bfloat16_rn(v.z);
    __nv_bfloat16 h3 = __float2bfloat16_rn(v.w);
    __nv_bfloat162* hp = reinterpret_cast<__nv_bfloat162*>(hi) + i * 2;
    __nv_bfloat162* lp = reinterpret_cast<__nv_bfloat162*>(lo) + i * 2;
    hp[0] = __nv_bfloat162(h0, h1);
    hp[1] = __nv_bfloat162(h2, h3);
    lp[0] = __nv_bfloat162(__float2bfloat16_rn(v.x - __bfloat162float(h0)),
                           __float2bfloat16_rn(v.y - __bfloat162float(h1)));
    lp[1] = __nv_bfloat162(__float2bfloat16_rn(v.z - __bfloat162float(h2)),
                           __float2bfloat16_rn(v.w - __bfloat162float(h3)));
}

// ---------------------------------------------------------------------------
// Kernel 1: Q = E @ Wq^T + bq, bf16-split 3-MMA via mma.sync (HMMA).
// CTA tile 128x128, BK=32, 8 warps (2x4), warp tile 64x32.
// Smem pitch 80 B -> conflict-free ldmatrix.
// ---------------------------------------------------------------------------
#define PIT 80                      // bytes per smem row (32 bf16 used + pad)
#define SA_HI 0
#define SA_LO 10240
#define SB_HI 20480
#define SB_LO 30720

__global__ __launch_bounds__(256) void qproj_hmma_kernel(
    const __nv_bfloat16* __restrict__ Ehi, const __nv_bfloat16* __restrict__ Elo,
    const __nv_bfloat16* __restrict__ Whi, const __nv_bfloat16* __restrict__ Wlo,
    const float* __restrict__ bq, int T)
{
    __shared__ __align__(16) char sm[40960];
    const uint32_t sb = smem_u32(sm);
    const int tid = threadIdx.x;
    const int wid = tid >> 5, lane = tid & 31;
    const int wm = wid & 1, wn = wid >> 1;      // 2 (M) x 4 (N) warp grid
    const int mbase = blockIdx.y * 128;
    const int nbase = blockIdx.x * 128;

    float acc[4][4][4];
#pragma unroll
    for (int mi = 0; mi < 4; mi++)
#pragma unroll
        for (int ni = 0; ni < 4; ni++)
#pragma unroll
            for (int q = 0; q < 4; q++) acc[mi][ni][q] = 0.f;

    // ldmatrix base offsets (per-lane), k-step term added in loop
    const uint32_t a_lane = (uint32_t)((wm * 64 + (lane & 15)) * PIT + (lane >> 4) * 16);
    const uint32_t b_lane = (uint32_t)((wn * 32 + (lane & 7) + ((lane >> 4) << 3)) * PIT +
                                       ((lane >> 3) & 1) * 16);

    for (int k0 = 0; k0 < D_DIM; k0 += 32) {
        // ---- stage 4 tiles: 128 rows x 32 bf16 each ----
#pragma unroll
        for (int i = 0; i < 2; i++) {
            int idx = i * 256 + tid;
            int r = idx >> 2, c4 = idx & 3;
            int ar = mbase + r; if (ar >= T) ar = T - 1;
            size_t ga = (size_t)ar * D_DIM + k0 + c4 * 8;
            size_t gb = (size_t)(nbase + r) * D_DIM + k0 + c4 * 8;
            uint32_t so = (uint32_t)(r * PIT + c4 * 16);
            *reinterpret_cast<uint4*>(sm + SA_HI + so) =
                *reinterpret_cast<const uint4*>(Ehi + ga);
            *reinterpret_cast<uint4*>(sm + SA_LO + so) =
                *reinterpret_cast<const uint4*>(Elo + ga);
            *reinterpret_cast<uint4*>(sm + SB_HI + so) =
                *reinterpret_cast<const uint4*>(Whi + gb);
            *reinterpret_cast<uint4*>(sm + SB_LO + so) =
                *reinterpret_cast<const uint4*>(Wlo + gb);
        }
        __syncthreads();

#pragma unroll
        for (int ks = 0; ks < 2; ks++) {
            const uint32_t ao = sb + a_lane + ks * 32;
            const uint32_t bo = sb + b_lane + ks * 32;
            uint32_t ah[4][4], al[4][4], bh[2][4], bl[2][4];

#pragma unroll
            for (int mi = 0; mi < 4; mi++) ldmx4(ah[mi], ao + SA_HI + mi * 16 * PIT);
#pragma unroll
            for (int np = 0; np < 2; np++) ldmx4(bh[np], bo + SB_HI + np * 16 * PIT);
            // hi * hi
#pragma unroll
            for (int mi = 0; mi < 4; mi++)
#pragma unroll
                for (int ni = 0; ni < 4; ni++)
                    mma16816(acc[mi][ni], ah[mi], &bh[ni >> 1][(ni & 1) * 2]);
            // hi * lo
#pragma unroll
            for (int np = 0; np < 2; np++) ldmx4(bl[np], bo + SB_LO + np * 16 * PIT);
#pragma unroll
            for (int mi = 0; mi < 4; mi++)
#pragma unroll
                for (int ni = 0; ni < 4; ni++)
                    mma16816(acc[mi][ni], ah[mi], &bl[ni >> 1][(ni & 1) * 2]);
            // lo * hi
#pragma unroll
            for (int mi = 0; mi < 4; mi++) ldmx4(al[mi], ao + SA_LO + mi * 16 * PIT);
#pragma unroll
            for (int mi = 0; mi < 4; mi++)
#pragma unroll
                for (int ni = 0; ni < 4; ni++)
                    mma16816(acc[mi][ni], al[mi], &bh[ni >> 1][(ni & 1) * 2]);
        }
        __syncthreads();
    }

    // ---- epilogue: add bq, store fp32 ----
    const int mrow0 = mbase + wm * 64 + (lane >> 2);
    const int ncol0 = nbase + wn * 32 + 2 * (lane & 3);
#pragma unroll
    for (int ni = 0; ni < 4; ni++) {
        int col = ncol0 + ni * 8;
        float2 bv = *reinterpret_cast<const float2*>(&bq[col]);
#pragma unroll
        for (int mi = 0; mi < 4; mi++) {
            int r0 = mrow0 + mi * 16;
            if (r0 < T) {
                float2 o0 = make_float2(acc[mi][ni][0] + bv.x, acc[mi][ni][1] + bv.y);
                *reinterpret_cast<float2*>(&g_Q[(size_t)r0 * D_DIM + col]) = o0;
            }
            if (r0 + 8 < T) {
                float2 o1 = make_float2(acc[mi][ni][2] + bv.x, acc[mi][ni][3] + bv.y);
                *reinterpret_cast<float2*>(&g_Q[(size_t)(r0 + 8) * D_DIM + col]) = o1;
            }
        }
    }
}

// ---------------------------------------------------------------------------
// Kernel 2: span attention (unchanged from R3 passing version, 362 us)
// ---------------------------------------------------------------------------
template<int NB>
__device__ __forceinline__ void scores_chunk(
    const float* __restrict__ Qc, const float* __restrict__ Ec,
    float (&acc)[NB][NB], int g, int sy, int sx)
{
    const float4* qb = reinterpret_cast<const float4*>(Qc + g * 48 + sy * CP);
    const float4* eb = reinterpret_cast<const float4*>(Ec + g * 48 + sx * CP);
#pragma unroll
    for (int kk = 0; kk < 12; kk++) {
        float4 a[NB];
#pragma unroll
        for (int i = 0; i < NB; i++) a[i] = qb[i * 8 * (CP / 4) + kk];
#pragma unroll
        for (int j = 0; j < NB; j++) {
            float4 b = eb[j * 8 * (CP / 4) + kk];
#pragma unroll
            for (int i = 0; i < NB; i++) {
                acc[i][j] += a[i].x * b.x;
                acc[i][j] += a[i].y * b.y;
                acc[i][j] += a[i].z * b.z;
                acc[i][j] += a[i].w * b.w;
            }
        }
    }
}

template<int NB>
__device__ __forceinline__ void span_scores(
    const float* __restrict__ E, float* Qc, float* Ec, float* Sb,
    int start, int len, int tid, int g, int sy, int sx)
{
    float acc[NB][NB];
#pragma unroll
    for (int i = 0; i < NB; i++)
#pragma unroll
        for (int j = 0; j < NB; j++) acc[i][j] = 0.f;

    const int tot4 = len * (CHUNK / 4);
    for (int c = 0; c < NCH; c++) {
        for (int idx = tid; idx < tot4; idx += NT) {
            int r = idx / (CHUNK / 4);
            int q4 = idx - r * (CHUNK / 4);
            size_t goff = (size_t)(start + r) * D_DIM + c * CHUNK + q4 * 4;
            reinterpret_cast<float4*>(Qc)[r * (CP / 4) + q4] =
                *reinterpret_cast<const float4*>(&g_Q[goff]);
            reinterpret_cast<float4*>(Ec)[r * (CP / 4) + q4] =
                *reinterpret_cast<const float4*>(&E[goff]);
        }
        __syncthreads();
        scores_chunk<NB>(Qc, Ec, acc, g, sy, sx);
        __syncthreads();
    }

    float* dst = Sb + g * 1056 + sy * 33 + sx;
#pragma unroll
    for (int i = 0; i < NB; i++)
#pragma unroll
        for (int j = 0; j < NB; j++)
            dst[i * 8 * 33 + j * 8] = acc[i][j];
}

__global__ __launch_bounds__(256, 3) void span_kernel(
    const float* __restrict__ E, const int* __restrict__ spans,
    float* __restrict__ out)
{
    extern __shared__ float smf[];
    float* Qc   = smf;
    float* Ec   = Qc + 32 * CP;
    float* Sb   = Ec + 32 * CP;
    float* S    = Sb + 4 * 1056;
    float* csum = S + 1056;

    const int n = blockIdx.x;
    const int tid = threadIdx.x;
    const int start = spans[2 * n];
    const int len   = spans[2 * n + 1] - start + 1;
    const int nb    = (len + 7) >> 3;

    const int g  = tid >> 6;
    const int s  = tid & 63;
    const int sy = s >> 3;
    const int sx = s & 7;

    switch (nb) {
        case 1: span_scores<1>(E, Qc, Ec, Sb, start, len, tid, g, sy, sx); break;
        case 2: span_scores<2>(E, Qc, Ec, Sb, start, len, tid, g, sy, sx); break;
        case 3: span_scores<3>(E, Qc, Ec, Sb, start, len, tid, g, sy, sx); break;
        default: span_scores<4>(E, Qc, Ec, Sb, start, len, tid, g, sy, sx); break;
    }
    __syncthreads();

    const int side = nb * 8;
    for (int idx = tid; idx < side * side; idx += NT) {
        int q = idx / side, k = idx - q * side;
        int o = q * 33 + k;
        S[o] = Sb[o] + Sb[1056 + o] + Sb[2112 + o] + Sb[3168 + o];
    }
    __syncthreads();

    const int warp = tid >> 5, lane = tid & 31;
#pragma unroll
    for (int r = 0; r < 4; r++) {
        int q = warp + 8 * r;
        if (q < len) {
            float x = (lane < len) ? S[q * 33 + lane] : -INFINITY;
            float m = x;
#pragma unroll
            for (int off = 16; off; off >>= 1)
                m = fmaxf(m, __shfl_xor_sync(0xffffffffu, m, off));
            float e = (lane < len) ? __expf(x - m) : 0.f;
            float ssum = e;
#pragma unroll
            for (int off = 16; off; off >>= 1)
                ssum += __shfl_xor_sync(0xffffffffu, ssum, off);
            S[q * 33 + lane] = e / ssum;
        }
    }
    __syncthreads();

    if (tid < 32) {
        float c = 0.f;
        if (tid < len)
            for (int q = 0; q < len; q++) c += S[q * 33 + tid];
        csum[tid] = c;
    }
    __syncthreads();

    {
        const float* eb = E + (size_t)start * D_DIM + tid;
        float a0 = 0.f, a1 = 0.f, a2 = 0.f;
        for (int k = 0; k < len; k++) {
            float w = csum[k];
            const float* p = eb + (size_t)k * D_DIM;
            a0 += w * p[0];
            a1 += w * p[256];
            a2 += w * p[512];
        }
        float* op = out + (size_t)n * D_DIM + tid;
        op[0]   = a0;
        op[256] = a1;
        op[512] = a2;
    }
}

// ---------------------------------------------------------------------------
// Launch
// ---------------------------------------------------------------------------
static const int SPAN_SMEM_BYTES =
    (2 * 32 * CP + 4 * 1056 + 1056 + 32) * (int)sizeof(float);   // 71424 B

extern "C" void kernel_launch(void* const* d_in, const int* in_sizes, int n_in,
                              void* d_out, int out_size)
{
    const float* E     = (const float*)d_in[0];
    const int*   spans = (const int*)d_in[1];
    const float* Wq    = (const float*)d_in[2];
    const float* bq    = (const float*)d_in[3];
    float*       out   = (float*)d_out;

    const int T = in_sizes[0] / D_DIM;
    const int N = in_sizes[1] / 2;

    __nv_bfloat16 *eh, *el, *wh, *wl;
    cudaGetSymbolAddress((void**)&eh, g_Ehi);
    cudaGetSymbolAddress((void**)&el, g_Elo);
    cudaGetSymbolAddress((void**)&wh, g_Whi);
    cudaGetSymbolAddress((void**)&wl, g_Wlo);

    // Split E and Wq into bf16 hi/lo
    {
        int n4 = T * D_DIM / 4;
        cvt_kernel<<<(n4 + 255) / 256, 256>>>(E, eh, el, n4);
        int w4 = D_DIM * D_DIM / 4;
        cvt_kernel<<<(w4 + 255) / 256, 256>>>(Wq, wh, wl, w4);
    }

    // Tensor-core Q projection (mma.sync HMMA)
    {
        dim3 gg(D_DIM / 128, (T + 127) / 128);
        qproj_hmma_kernel<<<gg, 256>>>(eh, el, wh, wl, bq, T);
    }

    cudaFuncSetAttribute(span_kernel,
                         cudaFuncAttributeMaxDynamicSharedMemorySize,
                         SPAN_SMEM_BYTES);
    span_kernel<<<N, 256, SPAN_SMEM_BYTES>>>(E, spans, out);
}

// round 6
// speedup vs baseline: 2.1943x; 1.2004x over previous
#include <cuda_runtime.h>
#include <cuda_bf16.h>
#include <math.h>
#include <stdint.h>

#define D_DIM 768
#define T_MAX 8192
#define NT 256

// Scratch (__device__ globals per harness rules)
__device__ __nv_bfloat16 g_Qhi[(size_t)T_MAX * D_DIM];
__device__ __nv_bfloat16 g_Qlo[(size_t)T_MAX * D_DIM];
__device__ __nv_bfloat16 g_Ehi[(size_t)T_MAX * D_DIM];
__device__ __nv_bfloat16 g_Elo[(size_t)T_MAX * D_DIM];
__device__ __nv_bfloat16 g_Whi[(size_t)D_DIM * D_DIM];
__device__ __nv_bfloat16 g_Wlo[(size_t)D_DIM * D_DIM];

// ---------------------------------------------------------------------------
// Helpers (baseline PTX only — plain sm_103 target, no tcgen05)
// ---------------------------------------------------------------------------
__device__ __forceinline__ uint32_t smem_u32(const void* p) {
    uint32_t a;
    asm("{ .reg .u64 t; cvta.to.shared.u64 t, %1; cvt.u32.u64 %0, t; }"
        : "=r"(a) : "l"(p));
    return a;
}
__device__ __forceinline__ void ldmx4(uint32_t* r, uint32_t addr) {
    asm volatile("ldmatrix.sync.aligned.m8n8.x4.shared.b16 {%0,%1,%2,%3}, [%4];"
                 : "=r"(r[0]), "=r"(r[1]), "=r"(r[2]), "=r"(r[3]) : "r"(addr));
}
__device__ __forceinline__ void mma16816(float* c, const uint32_t* a,
                                         const uint32_t* b) {
    asm volatile(
        "mma.sync.aligned.m16n8k16.row.col.f32.bf16.bf16.f32 "
        "{%0,%1,%2,%3}, {%4,%5,%6,%7}, {%8,%9}, {%0,%1,%2,%3};"
        : "+f"(c[0]), "+f"(c[1]), "+f"(c[2]), "+f"(c[3])
        : "r"(a[0]), "r"(a[1]), "r"(a[2]), "r"(a[3]), "r"(b[0]), "r"(b[1]));
}

// ---------------------------------------------------------------------------
// Kernel 0: fp32 -> (bf16 hi, bf16 lo) split
// ---------------------------------------------------------------------------
__global__ __launch_bounds__(256) void cvt_kernel(
    const float* __restrict__ src, __nv_bfloat16* __restrict__ hi,
    __nv_bfloat16* __restrict__ lo, int n4)
{
    int i = blockIdx.x * blockDim.x + threadIdx.x;
    if (i >= n4) return;
    float4 v = reinterpret_cast<const float4*>(src)[i];
    __nv_bfloat16 h0 = __float2bfloat16_rn(v.x);
    __nv_bfloat16 h1 = __float2bfloat16_rn(v.y);
    __nv_bfloat16 h2 = __float2bfloat16_rn(v.z);
    __nv_bfloat16 h3 = __float2bfloat16_rn(v.w);
    __nv_bfloat162* hp = reinterpret_cast<__nv_bfloat162*>(hi) + i * 2;
    __nv_bfloat162* lp = reinterpret_cast<__nv_bfloat162*>(lo) + i * 2;
    hp[0] = __nv_bfloat162(h0, h1);
    hp[1] = __nv_bfloat162(h2, h3);
    lp[0] = __nv_bfloat162(__float2bfloat16_rn(v.x - __bfloat162float(h0)),
                           __float2bfloat16_rn(v.y - __bfloat162float(h1)));
    lp[1] = __nv_bfloat162(__float2bfloat16_rn(v.z - __bfloat162float(h2)),
                           __float2bfloat16_rn(v.w - __bfloat162float(h3)));
}

// ---------------------------------------------------------------------------
// Kernel 1: Q = E @ Wq^T + bq via mma.sync, bf16-split 3-MMA.
// Epilogue writes Q as bf16 hi/lo pairs (for span-kernel HMMA scores).
// ---------------------------------------------------------------------------
#define PIT 80
#define SA_HI 0
#define SA_LO 10240
#define SB_HI 20480
#define SB_LO 30720

__global__ __launch_bounds__(256) void qproj_hmma_kernel(
    const __nv_bfloat16* __restrict__ Ehi, const __nv_bfloat16* __restrict__ Elo,
    const __nv_bfloat16* __restrict__ Whi, const __nv_bfloat16* __restrict__ Wlo,
    const float* __restrict__ bq, int T)
{
    __shared__ __align__(16) char sm[40960];
    const uint32_t sb = smem_u32(sm);
    const int tid = threadIdx.x;
    const int wid = tid >> 5, lane = tid & 31;
    const int wm = wid & 1, wn = wid >> 1;
    const int mbase = blockIdx.y * 128;
    const int nbase = blockIdx.x * 128;

    float acc[4][4][4];
#pragma unroll
    for (int mi = 0; mi < 4; mi++)
#pragma unroll
        for (int ni = 0; ni < 4; ni++)
#pragma unroll
            for (int q = 0; q < 4; q++) acc[mi][ni][q] = 0.f;

    const uint32_t a_lane = (uint32_t)((wm * 64 + (lane & 15)) * PIT + (lane >> 4) * 16);
    const uint32_t b_lane = (uint32_t)((wn * 32 + (lane & 7) + ((lane >> 4) << 3)) * PIT +
                                       ((lane >> 3) & 1) * 16);

    for (int k0 = 0; k0 < D_DIM; k0 += 32) {
#pragma unroll
        for (int i = 0; i < 2; i++) {
            int idx = i * 256 + tid;
            int r = idx >> 2, c4 = idx & 3;
            int ar = mbase + r; if (ar >= T) ar = T - 1;
            size_t ga = (size_t)ar * D_DIM + k0 + c4 * 8;
            size_t gb = (size_t)(nbase + r) * D_DIM + k0 + c4 * 8;
            uint32_t so = (uint32_t)(r * PIT + c4 * 16);
            *reinterpret_cast<uint4*>(sm + SA_HI + so) =
                *reinterpret_cast<const uint4*>(Ehi + ga);
            *reinterpret_cast<uint4*>(sm + SA_LO + so) =
                *reinterpret_cast<const uint4*>(Elo + ga);
            *reinterpret_cast<uint4*>(sm + SB_HI + so) =
                *reinterpret_cast<const uint4*>(Whi + gb);
            *reinterpret_cast<uint4*>(sm + SB_LO + so) =
                *reinterpret_cast<const uint4*>(Wlo + gb);
        }
        __syncthreads();

#pragma unroll
        for (int ks = 0; ks < 2; ks++) {
            const uint32_t ao = sb + a_lane + ks * 32;
            const uint32_t bo = sb + b_lane + ks * 32;
            uint32_t ah[4][4], al[4][4], bh[2][4], bl[2][4];
#pragma unroll
            for (int mi = 0; mi < 4; mi++) ldmx4(ah[mi], ao + SA_HI + mi * 16 * PIT);
#pragma unroll
            for (int np = 0; np < 2; np++) ldmx4(bh[np], bo + SB_HI + np * 16 * PIT);
#pragma unroll
            for (int mi = 0; mi < 4; mi++)
#pragma unroll
                for (int ni = 0; ni < 4; ni++)
                    mma16816(acc[mi][ni], ah[mi], &bh[ni >> 1][(ni & 1) * 2]);
#pragma unroll
            for (int np = 0; np < 2; np++) ldmx4(bl[np], bo + SB_LO + np * 16 * PIT);
#pragma unroll
            for (int mi = 0; mi < 4; mi++)
#pragma unroll
                for (int ni = 0; ni < 4; ni++)
                    mma16816(acc[mi][ni], ah[mi], &bl[ni >> 1][(ni & 1) * 2]);
#pragma unroll
            for (int mi = 0; mi < 4; mi++) ldmx4(al[mi], ao + SA_LO + mi * 16 * PIT);
#pragma unroll
            for (int mi = 0; mi < 4; mi++)
#pragma unroll
                for (int ni = 0; ni < 4; ni++)
                    mma16816(acc[mi][ni], al[mi], &bh[ni >> 1][(ni & 1) * 2]);
        }
        __syncthreads();
    }

    // Epilogue: add bq, split to bf16 hi/lo, store
    const int mrow0 = mbase + wm * 64 + (lane >> 2);
    const int ncol0 = nbase + wn * 32 + 2 * (lane & 3);
#pragma unroll
    for (int ni = 0; ni < 4; ni++) {
        int col = ncol0 + ni * 8;
        float2 bv = *reinterpret_cast<const float2*>(&bq[col]);
#pragma unroll
        for (int mi = 0; mi < 4; mi++) {
#pragma unroll
            for (int h = 0; h < 2; h++) {
                int r = mrow0 + mi * 16 + h * 8;
                if (r < T) {
                    float vx = acc[mi][ni][h * 2 + 0] + bv.x;
                    float vy = acc[mi][ni][h * 2 + 1] + bv.y;
                    __nv_bfloat16 hx = __float2bfloat16_rn(vx);
                    __nv_bfloat16 hy = __float2bfloat16_rn(vy);
                    size_t o = (size_t)r * D_DIM + col;
                    *reinterpret_cast<__nv_bfloat162*>(&g_Qhi[o]) = __nv_bfloat162(hx, hy);
                    *reinterpret_cast<__nv_bfloat162*>(&g_Qlo[o]) = __nv_bfloat162(
                        __float2bfloat16_rn(vx - __bfloat162float(hx)),
                        __float2bfloat16_rn(vy - __bfloat162float(hy)));
                }
            }
        }
    }
}

// ---------------------------------------------------------------------------
// Kernel 2: span attention with HMMA scores.
// Smem union layout (bytes):
//   [0, 16896)   Qhi stage  (32 rows x 528 B)     } after last chunk, first
//   [16896,33792) Qlo stage                        } 33792 B reused for 8
//   [33792,50688) Ehi stage                        } warp-partial tiles
//   [50688,67584) Elo stage
//   [67584,71808) S (32x33 f32)
//   [71808,71936) csum (32 f32)
// ---------------------------------------------------------------------------
#define SP_PIT   528
#define SP_ARR   16896
#define SP_S     67584
#define SP_CSUM  71808
#define SP_TOTAL 71936

template<int MT>
__device__ __forceinline__ void span_scores_hmma(
    char* sm, uint32_t sb,
    const __nv_bfloat16* __restrict__ Qh, const __nv_bfloat16* __restrict__ Ql,
    const __nv_bfloat16* __restrict__ Eh, const __nv_bfloat16* __restrict__ El,
    int start, int tid)
{
    const int w = tid >> 5, lane = tid & 31;
    const int R = 16 * MT;

    float acc[MT][2 * MT][4];
#pragma unroll
    for (int mi = 0; mi < MT; mi++)
#pragma unroll
        for (int ni = 0; ni < 2 * MT; ni++)
#pragma unroll
            for (int q = 0; q < 4; q++) acc[mi][ni][q] = 0.f;

    const uint32_t a_lane = (uint32_t)((lane & 15) * SP_PIT + (lane >> 4) * 16);
    const uint32_t b_lane = (uint32_t)(((lane & 7) + ((lane >> 4) << 3)) * SP_PIT +
                                       ((lane >> 3) & 1) * 16);

    for (int ch = 0; ch < 3; ch++) {
        // ---- stage 4 arrays x R rows x 256 dims (bf16, uint4 = 8 elems) ----
        const int iters = (4 * R * 32) / NT;      // MT=1: 8, MT=2: 16
#pragma unroll
        for (int i = 0; i < iters; i++) {
            int idx = i * NT + tid;
            int a = idx / (R * 32);
            int rem = idx - a * (R * 32);
            int r = rem >> 5, c = rem & 31;
            const __nv_bfloat16* src = (a == 0) ? Qh : (a == 1) ? Ql :
                                       (a == 2) ? Eh : El;
            *reinterpret_cast<uint4*>(sm + a * SP_ARR + r * SP_PIT + c * 16) =
                *reinterpret_cast<const uint4*>(
                    src + (size_t)(start + r) * D_DIM + ch * 256 + c * 8);
        }
        __syncthreads();

        // ---- MMA: warp w handles k-dims [32w, 32w+32) of this chunk ----
#pragma unroll
        for (int ks = 0; ks < 2; ks++) {
            const uint32_t kb = (uint32_t)((2 * w + ks) * 32);
            const uint32_t ao = sb + a_lane + kb;
            const uint32_t bo = sb + b_lane + kb;
            uint32_t ah[MT][4], al[MT][4], bh[MT][4], bl[MT][4];
#pragma unroll
            for (int mi = 0; mi < MT; mi++)
                ldmx4(ah[mi], ao + 0 * SP_ARR + mi * 16 * SP_PIT);
#pragma unroll
            for (int np = 0; np < MT; np++)
                ldmx4(bh[np], bo + 2 * SP_ARR + np * 16 * SP_PIT);
#pragma unroll
            for (int mi = 0; mi < MT; mi++)
#pragma unroll
                for (int ni = 0; ni < 2 * MT; ni++)
                    mma16816(acc[mi][ni], ah[mi], &bh[ni >> 1][(ni & 1) * 2]);
#pragma unroll
            for (int np = 0; np < MT; np++)
                ldmx4(bl[np], bo + 3 * SP_ARR + np * 16 * SP_PIT);
#pragma unroll
            for (int mi = 0; mi < MT; mi++)
#pragma unroll
                for (int ni = 0; ni < 2 * MT; ni++)
                    mma16816(acc[mi][ni], ah[mi], &bl[ni >> 1][(ni & 1) * 2]);
#pragma unroll
            for (int mi = 0; mi < MT; mi++)
                ldmx4(al[mi], ao + 1 * SP_ARR + mi * 16 * SP_PIT);
#pragma unroll
            for (int mi = 0; mi < MT; mi++)
#pragma unroll
                for (int ni = 0; ni < 2 * MT; ni++)
                    mma16816(acc[mi][ni], al[mi], &bh[ni >> 1][(ni & 1) * 2]);
        }
        __syncthreads();
    }

    // ---- store warp partials into (reused) staging region ----
    float* P = reinterpret_cast<float*>(sm) + w * 1056;
#pragma unroll
    for (int mi = 0; mi < MT; mi++)
#pragma unroll
        for (int ni = 0; ni < 2 * MT; ni++) {
            int r0 = mi * 16 + (lane >> 2);
            int col = ni * 8 + 2 * (lane & 3);
            P[r0 * 33 + col]           = acc[mi][ni][0];
            P[r0 * 33 + col + 1]       = acc[mi][ni][1];
            P[(r0 + 8) * 33 + col]     = acc[mi][ni][2];
            P[(r0 + 8) * 33 + col + 1] = acc[mi][ni][3];
        }
}

__global__ __launch_bounds__(256, 3) void span_kernel(
    const float* __restrict__ E, const int* __restrict__ spans,
    float* __restrict__ out)
{
    extern __shared__ __align__(16) char sm[];
    const uint32_t sb = smem_u32(sm);
    float* S    = reinterpret_cast<float*>(sm + SP_S);
    float* csum = reinterpret_cast<float*>(sm + SP_CSUM);

    const int n = blockIdx.x;
    const int tid = threadIdx.x;
    const int start = spans[2 * n];
    const int len   = spans[2 * n + 1] - start + 1;   // 1..32
    const int MTv   = (len > 16) ? 2 : 1;

    // device-global bf16 arrays (address via first element)
    if (MTv == 1)
        span_scores_hmma<1>(sm, sb, g_Qhi, g_Qlo, g_Ehi, g_Elo, start, tid);
    else
        span_scores_hmma<2>(sm, sb, g_Qhi, g_Qlo, g_Ehi, g_Elo, start, tid);
    __syncthreads();

    // ---- reduce 8 warp partials ----
    const int side = 16 * MTv;
    const float* P = reinterpret_cast<const float*>(sm);
    for (int idx = tid; idx < side * side; idx += NT) {
        int q = idx / side, k = idx - q * side;
        int o = q * 33 + k;
        float v = P[o];
#pragma unroll
        for (int w = 1; w < 8; w++) v += P[w * 1056 + o];
        S[o] = v;
    }
    __syncthreads();

    // ---- softmax over k (one warp per q-row) ----
    const int warp = tid >> 5, lane = tid & 31;
#pragma unroll
    for (int r = 0; r < 4; r++) {
        int q = warp + 8 * r;
        if (q < len) {
            float x = (lane < len) ? S[q * 33 + lane] : -INFINITY;
            float m = x;
#pragma unroll
            for (int off = 16; off; off >>= 1)
                m = fmaxf(m, __shfl_xor_sync(0xffffffffu, m, off));
            float e = (lane < len) ? __expf(x - m) : 0.f;
            float ssum = e;
#pragma unroll
            for (int off = 16; off; off >>= 1)
                ssum += __shfl_xor_sync(0xffffffffu, ssum, off);
            S[q * 33 + lane] = e / ssum;
        }
    }
    __syncthreads();

    // ---- column sums over valid q ----
    if (tid < 32) {
        float c = 0.f;
        if (tid < len)
            for (int q = 0; q < len; q++) c += S[q * 33 + tid];
        csum[tid] = c;
    }
    __syncthreads();

    // ---- out[n, d] = sum_k csum[k] * E[start + k, d]  (E fp32 via L2) ----
    {
        const float* eb = E + (size_t)start * D_DIM + tid;
        float a0 = 0.f, a1 = 0.f, a2 = 0.f;
        for (int k = 0; k < len; k++) {
            float w = csum[k];
            const float* p = eb + (size_t)k * D_DIM;
            a0 += w * p[0];
            a1 += w * p[256];
            a2 += w * p[512];
        }
        float* op = out + (size_t)n * D_DIM + tid;
        op[0]   = a0;
        op[256] = a1;
        op[512] = a2;
    }
}

// ---------------------------------------------------------------------------
// Launch
// ---------------------------------------------------------------------------
extern "C" void kernel_launch(void* const* d_in, const int* in_sizes, int n_in,
                              void* d_out, int out_size)
{
    const float* E     = (const float*)d_in[0];
    const int*   spans = (const int*)d_in[1];
    const float* Wq    = (const float*)d_in[2];
    const float* bq    = (const float*)d_in[3];
    float*       out   = (float*)d_out;

    const int T = in_sizes[0] / D_DIM;
    const int N = in_sizes[1] / 2;

    __nv_bfloat16 *eh, *el, *wh, *wl;
    cudaGetSymbolAddress((void**)&eh, g_Ehi);
    cudaGetSymbolAddress((void**)&el, g_Elo);
    cudaGetSymbolAddress((void**)&wh, g_Whi);
    cudaGetSymbolAddress((void**)&wl, g_Wlo);

    {
        int n4 = T * D_DIM / 4;
        cvt_kernel<<<(n4 + 255) / 256, 256>>>(E, eh, el, n4);
        int w4 = D_DIM * D_DIM / 4;
        cvt_kernel<<<(w4 + 255) / 256, 256>>>(Wq, wh, wl, w4);
    }

    {
        dim3 gg(D_DIM / 128, (T + 127) / 128);
        qproj_hmma_kernel<<<gg, 256>>>(eh, el, wh, wl, bq, T);
    }

    cudaFuncSetAttribute(span_kernel,
                         cudaFuncAttributeMaxDynamicSharedMemorySize, SP_TOTAL);
    span_kernel<<<N, 256, SP_TOTAL>>>(E, spans, out);
}

// round 7
// speedup vs baseline: 2.2077x; 1.0061x over previous
#include <cuda_runtime.h>
#include <cuda_bf16.h>
#include <math.h>
#include <stdint.h>

#define D_DIM 768
#define T_MAX 8192
#define NT 256

// Scratch (__device__ globals per harness rules)
__device__ __nv_bfloat16 g_Qhi[(size_t)T_MAX * D_DIM];
__device__ __nv_bfloat16 g_Qlo[(size_t)T_MAX * D_DIM];
__device__ __nv_bfloat16 g_Ehi[(size_t)T_MAX * D_DIM];
__device__ __nv_bfloat16 g_Elo[(size_t)T_MAX * D_DIM];
__device__ __nv_bfloat16 g_Whi[(size_t)D_DIM * D_DIM];
__device__ __nv_bfloat16 g_Wlo[(size_t)D_DIM * D_DIM];

// ---------------------------------------------------------------------------
// Helpers (baseline PTX only — plain sm_103 target, no tcgen05)
// ---------------------------------------------------------------------------
__device__ __forceinline__ uint32_t smem_u32(const void* p) {
    uint32_t a;
    asm("{ .reg .u64 t; cvta.to.shared.u64 t, %1; cvt.u32.u64 %0, t; }"
        : "=r"(a) : "l"(p));
    return a;
}
__device__ __forceinline__ void ldmx4(uint32_t* r, uint32_t addr) {
    asm volatile("ldmatrix.sync.aligned.m8n8.x4.shared.b16 {%0,%1,%2,%3}, [%4];"
                 : "=r"(r[0]), "=r"(r[1]), "=r"(r[2]), "=r"(r[3]) : "r"(addr));
}
__device__ __forceinline__ void mma16816(float* c, const uint32_t* a,
                                         const uint32_t* b) {
    asm volatile(
        "mma.sync.aligned.m16n8k16.row.col.f32.bf16.bf16.f32 "
        "{%0,%1,%2,%3}, {%4,%5,%6,%7}, {%8,%9}, {%0,%1,%2,%3};"
        : "+f"(c[0]), "+f"(c[1]), "+f"(c[2]), "+f"(c[3])
        : "r"(a[0]), "r"(a[1]), "r"(a[2]), "r"(a[3]), "r"(b[0]), "r"(b[1]));
}

// ---------------------------------------------------------------------------
// Kernel 0: fp32 -> (bf16 hi, bf16 lo) split
// ---------------------------------------------------------------------------
__global__ __launch_bounds__(256) void cvt_kernel(
    const float* __restrict__ src, __nv_bfloat16* __restrict__ hi,
    __nv_bfloat16* __restrict__ lo, int n4)
{
    int i = blockIdx.x * blockDim.x + threadIdx.x;
    if (i >= n4) return;
    float4 v = reinterpret_cast<const float4*>(src)[i];
    __nv_bfloat16 h0 = __float2bfloat16_rn(v.x);
    __nv_bfloat16 h1 = __float2bfloat16_rn(v.y);
    __nv_bfloat16 h2 = __float2bfloat16_rn(v.z);
    __nv_bfloat16 h3 = __float2bfloat16_rn(v.w);
    __nv_bfloat162* hp = reinterpret_cast<__nv_bfloat162*>(hi) + i * 2;
    __nv_bfloat162* lp = reinterpret_cast<__nv_bfloat162*>(lo) + i * 2;
    hp[0] = __nv_bfloat162(h0, h1);
    hp[1] = __nv_bfloat162(h2, h3);
    lp[0] = __nv_bfloat162(__float2bfloat16_rn(v.x - __bfloat162float(h0)),
                           __float2bfloat16_rn(v.y - __bfloat162float(h1)));
    lp[1] = __nv_bfloat162(__float2bfloat16_rn(v.z - __bfloat162float(h2)),
                           __float2bfloat16_rn(v.w - __bfloat162float(h3)));
}

// ---------------------------------------------------------------------------
// Kernel 1: Q = E @ Wq^T + bq via mma.sync, bf16-split 3-MMA.
// Epilogue writes Q as bf16 hi/lo pairs (for span-kernel HMMA scores).
// ---------------------------------------------------------------------------
#define PIT 80
#define SA_HI 0
#define SA_LO 10240
#define SB_HI 20480
#define SB_LO 30720

__global__ __launch_bounds__(256) void qproj_hmma_kernel(
    const __nv_bfloat16* __restrict__ Ehi, const __nv_bfloat16* __restrict__ Elo,
    const __nv_bfloat16* __restrict__ Whi, const __nv_bfloat16* __restrict__ Wlo,
    const float* __restrict__ bq, int T)
{
    __shared__ __align__(16) char sm[40960];
    const uint32_t sb = smem_u32(sm);
    const int tid = threadIdx.x;
    const int wid = tid >> 5, lane = tid & 31;
    const int wm = wid & 1, wn = wid >> 1;
    const int mbase = blockIdx.y * 128;
    const int nbase = blockIdx.x * 128;

    float acc[4][4][4];
#pragma unroll
    for (int mi = 0; mi < 4; mi++)
#pragma unroll
        for (int ni = 0; ni < 4; ni++)
#pragma unroll
            for (int q = 0; q < 4; q++) acc[mi][ni][q] = 0.f;

    const uint32_t a_lane = (uint32_t)((wm * 64 + (lane & 15)) * PIT + (lane >> 4) * 16);
    const uint32_t b_lane = (uint32_t)((wn * 32 + (lane & 7) + ((lane >> 4) << 3)) * PIT +
                                       ((lane >> 3) & 1) * 16);

    for (int k0 = 0; k0 < D_DIM; k0 += 32) {
#pragma unroll
        for (int i = 0; i < 2; i++) {
            int idx = i * 256 + tid;
            int r = idx >> 2, c4 = idx & 3;
            int ar = mbase + r; if (ar >= T) ar = T - 1;
            size_t ga = (size_t)ar * D_DIM + k0 + c4 * 8;
            size_t gb = (size_t)(nbase + r) * D_DIM + k0 + c4 * 8;
            uint32_t so = (uint32_t)(r * PIT + c4 * 16);
            *reinterpret_cast<uint4*>(sm + SA_HI + so) =
                *reinterpret_cast<const uint4*>(Ehi + ga);
            *reinterpret_cast<uint4*>(sm + SA_LO + so) =
                *reinterpret_cast<const uint4*>(Elo + ga);
            *reinterpret_cast<uint4*>(sm + SB_HI + so) =
                *reinterpret_cast<const uint4*>(Whi + gb);
            *reinterpret_cast<uint4*>(sm + SB_LO + so) =
                *reinterpret_cast<const uint4*>(Wlo + gb);
        }
        __syncthreads();

#pragma unroll
        for (int ks = 0; ks < 2; ks++) {
            const uint32_t ao = sb + a_lane + ks * 32;
            const uint32_t bo = sb + b_lane + ks * 32;
            uint32_t ah[4][4], al[4][4], bh[2][4], bl[2][4];
#pragma unroll
            for (int mi = 0; mi < 4; mi++) ldmx4(ah[mi], ao + SA_HI + mi * 16 * PIT);
#pragma unroll
            for (int np = 0; np < 2; np++) ldmx4(bh[np], bo + SB_HI + np * 16 * PIT);
#pragma unroll
            for (int mi = 0; mi < 4; mi++)
#pragma unroll
                for (int ni = 0; ni < 4; ni++)
                    mma16816(acc[mi][ni], ah[mi], &bh[ni >> 1][(ni & 1) * 2]);
#pragma unroll
            for (int np = 0; np < 2; np++) ldmx4(bl[np], bo + SB_LO + np * 16 * PIT);
#pragma unroll
            for (int mi = 0; mi < 4; mi++)
#pragma unroll
                for (int ni = 0; ni < 4; ni++)
                    mma16816(acc[mi][ni], ah[mi], &bl[ni >> 1][(ni & 1) * 2]);
#pragma unroll
            for (int mi = 0; mi < 4; mi++) ldmx4(al[mi], ao + SA_LO + mi * 16 * PIT);
#pragma unroll
            for (int mi = 0; mi < 4; mi++)
#pragma unroll
                for (int ni = 0; ni < 4; ni++)
                    mma16816(acc[mi][ni], al[mi], &bh[ni >> 1][(ni & 1) * 2]);
        }
        __syncthreads();
    }

    // Epilogue: add bq, split to bf16 hi/lo, store
    const int mrow0 = mbase + wm * 64 + (lane >> 2);
    const int ncol0 = nbase + wn * 32 + 2 * (lane & 3);
#pragma unroll
    for (int ni = 0; ni < 4; ni++) {
        int col = ncol0 + ni * 8;
        float2 bv = *reinterpret_cast<const float2*>(&bq[col]);
#pragma unroll
        for (int mi = 0; mi < 4; mi++) {
#pragma unroll
            for (int h = 0; h < 2; h++) {
                int r = mrow0 + mi * 16 + h * 8;
                if (r < T) {
                    float vx = acc[mi][ni][h * 2 + 0] + bv.x;
                    float vy = acc[mi][ni][h * 2 + 1] + bv.y;
                    __nv_bfloat16 hx = __float2bfloat16_rn(vx);
                    __nv_bfloat16 hy = __float2bfloat16_rn(vy);
                    size_t o = (size_t)r * D_DIM + col;
                    *reinterpret_cast<__nv_bfloat162*>(&g_Qhi[o]) = __nv_bfloat162(hx, hy);
                    *reinterpret_cast<__nv_bfloat162*>(&g_Qlo[o]) = __nv_bfloat162(
                        __float2bfloat16_rn(vx - __bfloat162float(hx)),
                        __float2bfloat16_rn(vy - __bfloat162float(hy)));
                }
            }
        }
    }
}

// ---------------------------------------------------------------------------
// Kernel 2: span attention with HMMA scores.
// Smem union layout (bytes):
//   [0, 16896)   Qhi stage  (32 rows x 528 B)     } after last chunk, first
//   [16896,33792) Qlo stage                        } 33792 B reused for 8
//   [33792,50688) Ehi stage                        } warp-partial tiles
//   [50688,67584) Elo stage
//   [67584,71808) S (32x33 f32)
//   [71808,71936) csum (32 f32)
// ---------------------------------------------------------------------------
#define SP_PIT   528
#define SP_ARR   16896
#define SP_S     67584
#define SP_CSUM  71808
#define SP_TOTAL 71936

template<int MT>
__device__ __forceinline__ void span_scores_hmma(
    char* sm, uint32_t sb,
    const __nv_bfloat16* __restrict__ Qh, const __nv_bfloat16* __restrict__ Ql,
    const __nv_bfloat16* __restrict__ Eh, const __nv_bfloat16* __restrict__ El,
    int start, int tid)
{
    const int w = tid >> 5, lane = tid & 31;
    const int R = 16 * MT;

    float acc[MT][2 * MT][4];
#pragma unroll
    for (int mi = 0; mi < MT; mi++)
#pragma unroll
        for (int ni = 0; ni < 2 * MT; ni++)
#pragma unroll
            for (int q = 0; q < 4; q++) acc[mi][ni][q] = 0.f;

    const uint32_t a_lane = (uint32_t)((lane & 15) * SP_PIT + (lane >> 4) * 16);
    const uint32_t b_lane = (uint32_t)(((lane & 7) + ((lane >> 4) << 3)) * SP_PIT +
                                       ((lane >> 3) & 1) * 16);

    for (int ch = 0; ch < 3; ch++) {
        // ---- stage 4 arrays x R rows x 256 dims (bf16, uint4 = 8 elems) ----
        const int iters = (4 * R * 32) / NT;      // MT=1: 8, MT=2: 16
#pragma unroll
        for (int i = 0; i < iters; i++) {
            int idx = i * NT + tid;
            int a = idx / (R * 32);
            int rem = idx - a * (R * 32);
            int r = rem >> 5, c = rem & 31;
            const __nv_bfloat16* src = (a == 0) ? Qh : (a == 1) ? Ql :
                                       (a == 2) ? Eh : El;
            *reinterpret_cast<uint4*>(sm + a * SP_ARR + r * SP_PIT + c * 16) =
                *reinterpret_cast<const uint4*>(
                    src + (size_t)(start + r) * D_DIM + ch * 256 + c * 8);
        }
        __syncthreads();

        // ---- MMA: warp w handles k-dims [32w, 32w+32) of this chunk ----
#pragma unroll
        for (int ks = 0; ks < 2; ks++) {
            const uint32_t kb = (uint32_t)((2 * w + ks) * 32);
            const uint32_t ao = sb + a_lane + kb;
            const uint32_t bo = sb + b_lane + kb;
            uint32_t ah[MT][4], al[MT][4], bh[MT][4], bl[MT][4];
#pragma unroll
            for (int mi = 0; mi < MT; mi++)
                ldmx4(ah[mi], ao + 0 * SP_ARR + mi * 16 * SP_PIT);
#pragma unroll
            for (int np = 0; np < MT; np++)
                ldmx4(bh[np], bo + 2 * SP_ARR + np * 16 * SP_PIT);
#pragma unroll
            for (int mi = 0; mi < MT; mi++)
#pragma unroll
                for (int ni = 0; ni < 2 * MT; ni++)
                    mma16816(acc[mi][ni], ah[mi], &bh[ni >> 1][(ni & 1) * 2]);
#pragma unroll
            for (int np = 0; np < MT; np++)
                ldmx4(bl[np], bo + 3 * SP_ARR + np * 16 * SP_PIT);
#pragma unroll
            for (int mi = 0; mi < MT; mi++)
#pragma unroll
                for (int ni = 0; ni < 2 * MT; ni++)
                    mma16816(acc[mi][ni], ah[mi], &bl[ni >> 1][(ni & 1) * 2]);
#pragma unroll
            for (int mi = 0; mi < MT; mi++)
                ldmx4(al[mi], ao + 1 * SP_ARR + mi * 16 * SP_PIT);
#pragma unroll
            for (int mi = 0; mi < MT; mi++)
#pragma unroll
                for (int ni = 0; ni < 2 * MT; ni++)
                    mma16816(acc[mi][ni], al[mi], &bh[ni >> 1][(ni & 1) * 2]);
        }
        __syncthreads();
    }

    // ---- store warp partials into (reused) staging region ----
    float* P = reinterpret_cast<float*>(sm) + w * 1056;
#pragma unroll
    for (int mi = 0; mi < MT; mi++)
#pragma unroll
        for (int ni = 0; ni < 2 * MT; ni++) {
            int r0 = mi * 16 + (lane >> 2);
            int col = ni * 8 + 2 * (lane & 3);
            P[r0 * 33 + col]           = acc[mi][ni][0];
            P[r0 * 33 + col + 1]       = acc[mi][ni][1];
            P[(r0 + 8) * 33 + col]     = acc[mi][ni][2];
            P[(r0 + 8) * 33 + col + 1] = acc[mi][ni][3];
        }
}

__global__ __launch_bounds__(256, 3) void span_kernel(
    const float* __restrict__ E, const int* __restrict__ spans,
    float* __restrict__ out)
{
    extern __shared__ __align__(16) char sm[];
    const uint32_t sb = smem_u32(sm);
    float* S    = reinterpret_cast<float*>(sm + SP_S);
    float* csum = reinterpret_cast<float*>(sm + SP_CSUM);

    const int n = blockIdx.x;
    const int tid = threadIdx.x;
    const int start = spans[2 * n];
    const int len   = spans[2 * n + 1] - start + 1;   // 1..32
    const int MTv   = (len > 16) ? 2 : 1;

    // device-global bf16 arrays (address via first element)
    if (MTv == 1)
        span_scores_hmma<1>(sm, sb, g_Qhi, g_Qlo, g_Ehi, g_Elo, start, tid);
    else
        span_scores_hmma<2>(sm, sb, g_Qhi, g_Qlo, g_Ehi, g_Elo, start, tid);
    __syncthreads();

    // ---- reduce 8 warp partials ----
    const int side = 16 * MTv;
    const float* P = reinterpret_cast<const float*>(sm);
    for (int idx = tid; idx < side * side; idx += NT) {
        int q = idx / side, k = idx - q * side;
        int o = q * 33 + k;
        float v = P[o];
#pragma unroll
        for (int w = 1; w < 8; w++) v += P[w * 1056 + o];
        S[o] = v;
    }
    __syncthreads();

    // ---- softmax over k (one warp per q-row) ----
    const int warp = tid >> 5, lane = tid & 31;
#pragma unroll
    for (int r = 0; r < 4; r++) {
        int q = warp + 8 * r;
        if (q < len) {
            float x = (lane < len) ? S[q * 33 + lane] : -INFINITY;
            float m = x;
#pragma unroll
            for (int off = 16; off; off >>= 1)
                m = fmaxf(m, __shfl_xor_sync(0xffffffffu, m, off));
            float e = (lane < len) ? __expf(x - m) : 0.f;
            float ssum = e;
#pragma unroll
            for (int off = 16; off; off >>= 1)
                ssum += __shfl_xor_sync(0xffffffffu, ssum, off);
            S[q * 33 + lane] = e / ssum;
        }
    }
    __syncthreads();

    // ---- column sums over valid q ----
    if (tid < 32) {
        float c = 0.f;
        if (tid < len)
            for (int q = 0; q < len; q++) c += S[q * 33 + tid];
        csum[tid] = c;
    }
    __syncthreads();

    // ---- out[n, d] = sum_k csum[k] * E[start + k, d]  (E fp32 via L2) ----
    {
        const float* eb = E + (size_t)start * D_DIM + tid;
        float a0 = 0.f, a1 = 0.f, a2 = 0.f;
        for (int k = 0; k < len; k++) {
            float w = csum[k];
            const float* p = eb + (size_t)k * D_DIM;
            a0 += w * p[0];
            a1 += w * p[256];
            a2 += w * p[512];
        }
        float* op = out + (size_t)n * D_DIM + tid;
        op[0]   = a0;
        op[256] = a1;
        op[512] = a2;
    }
}

// ---------------------------------------------------------------------------
// Launch
// ---------------------------------------------------------------------------
extern "C" void kernel_launch(void* const* d_in, const int* in_sizes, int n_in,
                              void* d_out, int out_size)
{
    const float* E     = (const float*)d_in[0];
    const int*   spans = (const int*)d_in[1];
    const float* Wq    = (const float*)d_in[2];
    const float* bq    = (const float*)d_in[3];
    float*       out   = (float*)d_out;

    const int T = in_sizes[0] / D_DIM;
    const int N = in_sizes[1] / 2;

    __nv_bfloat16 *eh, *el, *wh, *wl;
    cudaGetSymbolAddress((void**)&eh, g_Ehi);
    cudaGetSymbolAddress((void**)&el, g_Elo);
    cudaGetSymbolAddress((void**)&wh, g_Whi);
    cudaGetSymbolAddress((void**)&wl, g_Wlo);

    {
        int n4 = T * D_DIM / 4;
        cvt_kernel<<<(n4 + 255) / 256, 256>>>(E, eh, el, n4);
        int w4 = D_DIM * D_DIM / 4;
        cvt_kernel<<<(w4 + 255) / 256, 256>>>(Wq, wh, wl, w4);
    }

    {
        dim3 gg(D_DIM / 128, (T + 127) / 128);
        qproj_hmma_kernel<<<gg, 256>>>(eh, el, wh, wl, bq, T);
    }

    cudaFuncSetAttribute(span_kernel,
                         cudaFuncAttributeMaxDynamicSharedMemorySize, SP_TOTAL);
    span_kernel<<<N, 256, SP_TOTAL>>>(E, spans, out);
}

// round 8
// speedup vs baseline: 2.4802x; 1.1234x over previous
#include <cuda_runtime.h>
#include <cuda_bf16.h>
#include <math.h>
#include <stdint.h>

#define D_DIM 768
#define T_MAX 8192
#define NT 256

// Scratch (__device__ globals per harness rules)
__device__ __nv_bfloat16 g_Qhi[(size_t)T_MAX * D_DIM];
__device__ __nv_bfloat16 g_Qlo[(size_t)T_MAX * D_DIM];
__device__ __nv_bfloat16 g_Ehi[(size_t)T_MAX * D_DIM];
__device__ __nv_bfloat16 g_Elo[(size_t)T_MAX * D_DIM];
__device__ __nv_bfloat16 g_Whi[(size_t)D_DIM * D_DIM];
__device__ __nv_bfloat16 g_Wlo[(size_t)D_DIM * D_DIM];

// ---------------------------------------------------------------------------
// Helpers (baseline PTX only — plain sm_103 target)
// ---------------------------------------------------------------------------
__device__ __forceinline__ uint32_t smem_u32(const void* p) {
    uint32_t a;
    asm("{ .reg .u64 t; cvta.to.shared.u64 t, %1; cvt.u32.u64 %0, t; }"
        : "=r"(a) : "l"(p));
    return a;
}
__device__ __forceinline__ void ldmx4(uint32_t* r, uint32_t addr) {
    asm volatile("ldmatrix.sync.aligned.m8n8.x4.shared.b16 {%0,%1,%2,%3}, [%4];"
                 : "=r"(r[0]), "=r"(r[1]), "=r"(r[2]), "=r"(r[3]) : "r"(addr));
}
__device__ __forceinline__ void mma16816(float* c, const uint32_t* a,
                                         const uint32_t* b) {
    asm volatile(
        "mma.sync.aligned.m16n8k16.row.col.f32.bf16.bf16.f32 "
        "{%0,%1,%2,%3}, {%4,%5,%6,%7}, {%8,%9}, {%0,%1,%2,%3};"
        : "+f"(c[0]), "+f"(c[1]), "+f"(c[2]), "+f"(c[3])
        : "r"(a[0]), "r"(a[1]), "r"(a[2]), "r"(a[3]), "r"(b[0]), "r"(b[1]));
}
__device__ __forceinline__ void cp16(uint32_t dst, const void* src) {
    asm volatile("cp.async.cg.shared.global [%0], [%1], 16;"
                 :: "r"(dst), "l"(src) : "memory");
}
#define CP_COMMIT() asm volatile("cp.async.commit_group;" ::: "memory")
#define CP_WAIT0()  asm volatile("cp.async.wait_group 0;" ::: "memory")
#define CP_WAIT1()  asm volatile("cp.async.wait_group 1;" ::: "memory")

// ---------------------------------------------------------------------------
// Kernel 0: fp32 -> (bf16 hi, bf16 lo) split
// ---------------------------------------------------------------------------
__global__ __launch_bounds__(256) void cvt_kernel(
    const float* __restrict__ src, __nv_bfloat16* __restrict__ hi,
    __nv_bfloat16* __restrict__ lo, int n4)
{
    int i = blockIdx.x * blockDim.x + threadIdx.x;
    if (i >= n4) return;
    float4 v = reinterpret_cast<const float4*>(src)[i];
    __nv_bfloat16 h0 = __float2bfloat16_rn(v.x);
    __nv_bfloat16 h1 = __float2bfloat16_rn(v.y);
    __nv_bfloat16 h2 = __float2bfloat16_rn(v.z);
    __nv_bfloat16 h3 = __float2bfloat16_rn(v.w);
    __nv_bfloat162* hp = reinterpret_cast<__nv_bfloat162*>(hi) + i * 2;
    __nv_bfloat162* lp = reinterpret_cast<__nv_bfloat162*>(lo) + i * 2;
    hp[0] = __nv_bfloat162(h0, h1);
    hp[1] = __nv_bfloat162(h2, h3);
    lp[0] = __nv_bfloat162(__float2bfloat16_rn(v.x - __bfloat162float(h0)),
                           __float2bfloat16_rn(v.y - __bfloat162float(h1)));
    lp[1] = __nv_bfloat162(__float2bfloat16_rn(v.z - __bfloat162float(h2)),
                           __float2bfloat16_rn(v.w - __bfloat162float(h3)));
}

// ---------------------------------------------------------------------------
// Kernel 1: Q = E @ Wq^T + bq (HMMA, bf16-split 3-MMA), cp.async 2-stage
// pipeline. CTA tile 128x128, BK=32, 8 warps (2x4).
// ---------------------------------------------------------------------------
#define PIT 80
#define SA_HI 0
#define SA_LO 10240
#define SB_HI 20480
#define SB_LO 30720
#define QS_STAGE 40960        // bytes per pipeline stage
#define QS_TOTAL 81920

__global__ __launch_bounds__(256, 2) void qproj_hmma_kernel(
    const __nv_bfloat16* __restrict__ Ehi, const __nv_bfloat16* __restrict__ Elo,
    const __nv_bfloat16* __restrict__ Whi, const __nv_bfloat16* __restrict__ Wlo,
    const float* __restrict__ bq, int T)
{
    extern __shared__ __align__(16) char qsm[];
    const uint32_t sb = smem_u32(qsm);
    const int tid = threadIdx.x;
    const int wid = tid >> 5, lane = tid & 31;
    const int wm = wid & 1, wn = wid >> 1;
    const int mbase = blockIdx.y * 128;
    const int nbase = blockIdx.x * 128;

    float acc[4][4][4];
#pragma unroll
    for (int mi = 0; mi < 4; mi++)
#pragma unroll
        for (int ni = 0; ni < 4; ni++)
#pragma unroll
            for (int q = 0; q < 4; q++) acc[mi][ni][q] = 0.f;

    const uint32_t a_lane = (uint32_t)((wm * 64 + (lane & 15)) * PIT + (lane >> 4) * 16);
    const uint32_t b_lane = (uint32_t)((wn * 32 + (lane & 7) + ((lane >> 4) << 3)) * PIT +
                                       ((lane >> 3) & 1) * 16);

    auto stage_chunk = [&](int c) {
        const int k0 = c * 32;
        const uint32_t db = sb + (uint32_t)(c & 1) * QS_STAGE;
#pragma unroll
        for (int i = 0; i < 2; i++) {
            int idx = i * 256 + tid;
            int r = idx >> 2, c4 = idx & 3;
            int ar = mbase + r; if (ar >= T) ar = T - 1;
            size_t ga = (size_t)ar * D_DIM + k0 + c4 * 8;
            size_t gb = (size_t)(nbase + r) * D_DIM + k0 + c4 * 8;
            uint32_t so = (uint32_t)(r * PIT + c4 * 16);
            cp16(db + SA_HI + so, Ehi + ga);
            cp16(db + SA_LO + so, Elo + ga);
            cp16(db + SB_HI + so, Whi + gb);
            cp16(db + SB_LO + so, Wlo + gb);
        }
    };

    stage_chunk(0);
    CP_COMMIT();

    const int NC = D_DIM / 32;    // 24
    for (int c = 0; c < NC; c++) {
        if (c + 1 < NC) { stage_chunk(c + 1); CP_COMMIT(); CP_WAIT1(); }
        else            { CP_WAIT0(); }
        __syncthreads();

        const uint32_t st = sb + (uint32_t)(c & 1) * QS_STAGE;
#pragma unroll
        for (int ks = 0; ks < 2; ks++) {
            const uint32_t ao = st + a_lane + ks * 32;
            const uint32_t bo = st + b_lane + ks * 32;
            uint32_t ah[4][4], al[4][4], bh[2][4], bl[2][4];
#pragma unroll
            for (int mi = 0; mi < 4; mi++) ldmx4(ah[mi], ao + SA_HI + mi * 16 * PIT);
#pragma unroll
            for (int np = 0; np < 2; np++) ldmx4(bh[np], bo + SB_HI + np * 16 * PIT);
#pragma unroll
            for (int mi = 0; mi < 4; mi++)
#pragma unroll
                for (int ni = 0; ni < 4; ni++)
                    mma16816(acc[mi][ni], ah[mi], &bh[ni >> 1][(ni & 1) * 2]);
#pragma unroll
            for (int np = 0; np < 2; np++) ldmx4(bl[np], bo + SB_LO + np * 16 * PIT);
#pragma unroll
            for (int mi = 0; mi < 4; mi++)
#pragma unroll
                for (int ni = 0; ni < 4; ni++)
                    mma16816(acc[mi][ni], ah[mi], &bl[ni >> 1][(ni & 1) * 2]);
#pragma unroll
            for (int mi = 0; mi < 4; mi++) ldmx4(al[mi], ao + SA_LO + mi * 16 * PIT);
#pragma unroll
            for (int mi = 0; mi < 4; mi++)
#pragma unroll
                for (int ni = 0; ni < 4; ni++)
                    mma16816(acc[mi][ni], al[mi], &bh[ni >> 1][(ni & 1) * 2]);
        }
        __syncthreads();
    }

    // Epilogue: add bq, split to bf16 hi/lo, store
    const int mrow0 = mbase + wm * 64 + (lane >> 2);
    const int ncol0 = nbase + wn * 32 + 2 * (lane & 3);
#pragma unroll
    for (int ni = 0; ni < 4; ni++) {
        int col = ncol0 + ni * 8;
        float2 bv = *reinterpret_cast<const float2*>(&bq[col]);
#pragma unroll
        for (int mi = 0; mi < 4; mi++) {
#pragma unroll
            for (int h = 0; h < 2; h++) {
                int r = mrow0 + mi * 16 + h * 8;
                if (r < T) {
                    float vx = acc[mi][ni][h * 2 + 0] + bv.x;
                    float vy = acc[mi][ni][h * 2 + 1] + bv.y;
                    __nv_bfloat16 hx = __float2bfloat16_rn(vx);
                    __nv_bfloat16 hy = __float2bfloat16_rn(vy);
                    size_t o = (size_t)r * D_DIM + col;
                    *reinterpret_cast<__nv_bfloat162*>(&g_Qhi[o]) = __nv_bfloat162(hx, hy);
                    *reinterpret_cast<__nv_bfloat162*>(&g_Qlo[o]) = __nv_bfloat162(
                        __float2bfloat16_rn(vx - __bfloat162float(hx)),
                        __float2bfloat16_rn(vy - __bfloat162float(hy)));
                }
            }
        }
    }
}

// ---------------------------------------------------------------------------
// Kernel 2: span attention with HMMA scores, NBc-templated (len-proportional
// staging + MMA), cp.async staging.
// Smem layout (bytes):
//   [0, 16896)    Qhi stage (32 rows x 528 B)   } first 33792 B reused for
//   [16896,33792) Qlo stage                      } 8 warp-partial tiles
//   [33792,50688) Ehi stage
//   [50688,67584) Elo stage
//   [67584,71808) S (32x33 f32)
//   [71808,71936) csum
// ---------------------------------------------------------------------------
#define SP_PIT   528
#define SP_ARR   16896
#define SP_S     67584
#define SP_CSUM  71808
#define SP_TOTAL 71936

template<int NBc>
__device__ __forceinline__ void span_scores_hmma(
    char* sm, uint32_t sb,
    const __nv_bfloat16* __restrict__ Qh, const __nv_bfloat16* __restrict__ Ql,
    const __nv_bfloat16* __restrict__ Eh, const __nv_bfloat16* __restrict__ El,
    int start, int tid)
{
    constexpr int MT = (NBc + 1) / 2;     // A m16-tiles
    constexpr int R8 = 8 * NBc;           // rows staged
    const int w = tid >> 5, lane = tid & 31;

    float acc[MT][NBc][4];
#pragma unroll
    for (int mi = 0; mi < MT; mi++)
#pragma unroll
        for (int ni = 0; ni < NBc; ni++)
#pragma unroll
            for (int q = 0; q < 4; q++) acc[mi][ni][q] = 0.f;

    const uint32_t a_lane = (uint32_t)((lane & 15) * SP_PIT + (lane >> 4) * 16);
    const uint32_t b_lane = (uint32_t)(((lane & 7) + ((lane >> 4) << 3)) * SP_PIT +
                                       ((lane >> 3) & 1) * 16);

    for (int ch = 0; ch < 3; ch++) {
        // ---- stage 4 arrays x R8 rows x 256 dims via cp.async ----
#pragma unroll
        for (int i = 0; i < 4 * NBc; i++) {
            int idx = i * NT + tid;
            int a = idx / (R8 * 32);
            int rem = idx - a * (R8 * 32);
            int r = rem >> 5, c = rem & 31;
            const __nv_bfloat16* src = (a == 0) ? Qh : (a == 1) ? Ql :
                                       (a == 2) ? Eh : El;
            cp16(sb + a * SP_ARR + r * SP_PIT + c * 16,
                 src + (size_t)(start + r) * D_DIM + ch * 256 + c * 8);
        }
        CP_COMMIT();
        CP_WAIT0();
        __syncthreads();

        // ---- MMA: warp w owns k-dims [32w, 32w+32) of this chunk ----
#pragma unroll
        for (int ks = 0; ks < 2; ks++) {
            const uint32_t kb = (uint32_t)(w * 64 + ks * 32);
            const uint32_t ao = sb + a_lane + kb;
            const uint32_t bo = sb + b_lane + kb;
            uint32_t ah[MT][4], al[MT][4], bh[MT][4], bl[MT][4];
#pragma unroll
            for (int mi = 0; mi < MT; mi++)
                ldmx4(ah[mi], ao + 0 * SP_ARR + mi * 16 * SP_PIT);
#pragma unroll
            for (int np = 0; np < MT; np++)
                ldmx4(bh[np], bo + 2 * SP_ARR + np * 16 * SP_PIT);
#pragma unroll
            for (int mi = 0; mi < MT; mi++)
#pragma unroll
                for (int ni = 0; ni < NBc; ni++)
                    mma16816(acc[mi][ni], ah[mi], &bh[ni >> 1][(ni & 1) * 2]);
#pragma unroll
            for (int np = 0; np < MT; np++)
                ldmx4(bl[np], bo + 3 * SP_ARR + np * 16 * SP_PIT);
#pragma unroll
            for (int mi = 0; mi < MT; mi++)
#pragma unroll
                for (int ni = 0; ni < NBc; ni++)
                    mma16816(acc[mi][ni], ah[mi], &bl[ni >> 1][(ni & 1) * 2]);
#pragma unroll
            for (int mi = 0; mi < MT; mi++)
                ldmx4(al[mi], ao + 1 * SP_ARR + mi * 16 * SP_PIT);
#pragma unroll
            for (int mi = 0; mi < MT; mi++)
#pragma unroll
                for (int ni = 0; ni < NBc; ni++)
                    mma16816(acc[mi][ni], al[mi], &bh[ni >> 1][(ni & 1) * 2]);
        }
        __syncthreads();
    }

    // ---- store warp partials into (reused) staging region ----
    float* P = reinterpret_cast<float*>(sm) + w * 1056;
#pragma unroll
    for (int mi = 0; mi < MT; mi++)
#pragma unroll
        for (int ni = 0; ni < NBc; ni++) {
            int r0 = mi * 16 + (lane >> 2);
            int col = ni * 8 + 2 * (lane & 3);
            P[r0 * 33 + col]           = acc[mi][ni][0];
            P[r0 * 33 + col + 1]       = acc[mi][ni][1];
            P[(r0 + 8) * 33 + col]     = acc[mi][ni][2];
            P[(r0 + 8) * 33 + col + 1] = acc[mi][ni][3];
        }
}

__global__ __launch_bounds__(256, 3) void span_kernel(
    const float* __restrict__ E, const int* __restrict__ spans,
    float* __restrict__ out)
{
    extern __shared__ __align__(16) char sm[];
    const uint32_t sb = smem_u32(sm);
    float* S    = reinterpret_cast<float*>(sm + SP_S);
    float* csum = reinterpret_cast<float*>(sm + SP_CSUM);

    const int n = blockIdx.x;
    const int tid = threadIdx.x;
    const int start = spans[2 * n];
    const int len   = spans[2 * n + 1] - start + 1;   // 1..32
    const int nbc   = (len + 7) >> 3;                 // 1..4

    switch (nbc) {
        case 1: span_scores_hmma<1>(sm, sb, g_Qhi, g_Qlo, g_Ehi, g_Elo, start, tid); break;
        case 2: span_scores_hmma<2>(sm, sb, g_Qhi, g_Qlo, g_Ehi, g_Elo, start, tid); break;
        case 3: span_scores_hmma<3>(sm, sb, g_Qhi, g_Qlo, g_Ehi, g_Elo, start, tid); break;
        default: span_scores_hmma<4>(sm, sb, g_Qhi, g_Qlo, g_Ehi, g_Elo, start, tid); break;
    }
    __syncthreads();

    // ---- reduce 8 warp partials (only len rows x side cols) ----
    const int side = nbc * 8;
    const float* P = reinterpret_cast<const float*>(sm);
    for (int idx = tid; idx < len * side; idx += NT) {
        int q = idx / side, k = idx - q * side;
        int o = q * 33 + k;
        float v = P[o];
#pragma unroll
        for (int w = 1; w < 8; w++) v += P[w * 1056 + o];
        S[o] = v;
    }
    __syncthreads();

    // ---- softmax over k (one warp per q-row) ----
    const int warp = tid >> 5, lane = tid & 31;
#pragma unroll
    for (int r = 0; r < 4; r++) {
        int q = warp + 8 * r;
        if (q < len) {
            float x = (lane < len) ? S[q * 33 + lane] : -INFINITY;
            float m = x;
#pragma unroll
            for (int off = 16; off; off >>= 1)
                m = fmaxf(m, __shfl_xor_sync(0xffffffffu, m, off));
            float e = (lane < len) ? __expf(x - m) : 0.f;
            float ssum = e;
#pragma unroll
            for (int off = 16; off; off >>= 1)
                ssum += __shfl_xor_sync(0xffffffffu, ssum, off);
            S[q * 33 + lane] = e / ssum;
        }
    }
    __syncthreads();

    // ---- column sums over valid q ----
    if (tid < 32) {
        float c = 0.f;
        if (tid < len)
            for (int q = 0; q < len; q++) c += S[q * 33 + tid];
        csum[tid] = c;
    }
    __syncthreads();

    // ---- out[n, d] = sum_k csum[k] * E[start + k, d]  (E fp32 via L2) ----
    {
        const float* eb = E + (size_t)start * D_DIM + tid;
        float a0 = 0.f, a1 = 0.f, a2 = 0.f;
        for (int k = 0; k < len; k++) {
            float w = csum[k];
            const float* p = eb + (size_t)k * D_DIM;
            a0 += w * p[0];
            a1 += w * p[256];
            a2 += w * p[512];
        }
        float* op = out + (size_t)n * D_DIM + tid;
        op[0]   = a0;
        op[256] = a1;
        op[512] = a2;
    }
}

// ---------------------------------------------------------------------------
// Launch
// ---------------------------------------------------------------------------
extern "C" void kernel_launch(void* const* d_in, const int* in_sizes, int n_in,
                              void* d_out, int out_size)
{
    const float* E     = (const float*)d_in[0];
    const int*   spans = (const int*)d_in[1];
    const float* Wq    = (const float*)d_in[2];
    const float* bq    = (const float*)d_in[3];
    float*       out   = (float*)d_out;

    const int T = in_sizes[0] / D_DIM;
    const int N = in_sizes[1] / 2;

    __nv_bfloat16 *eh, *el, *wh, *wl;
    cudaGetSymbolAddress((void**)&eh, g_Ehi);
    cudaGetSymbolAddress((void**)&el, g_Elo);
    cudaGetSymbolAddress((void**)&wh, g_Whi);
    cudaGetSymbolAddress((void**)&wl, g_Wlo);

    {
        int n4 = T * D_DIM / 4;
        cvt_kernel<<<(n4 + 255) / 256, 256>>>(E, eh, el, n4);
        int w4 = D_DIM * D_DIM / 4;
        cvt_kernel<<<(w4 + 255) / 256, 256>>>(Wq, wh, wl, w4);
    }

    {
        cudaFuncSetAttribute(qproj_hmma_kernel,
                             cudaFuncAttributeMaxDynamicSharedMemorySize, QS_TOTAL);
        dim3 gg(D_DIM / 128, (T + 127) / 128);
        qproj_hmma_kernel<<<gg, 256, QS_TOTAL>>>(eh, el, wh, wl, bq, T);
    }

    cudaFuncSetAttribute(span_kernel,
                         cudaFuncAttributeMaxDynamicSharedMemorySize, SP_TOTAL);
    span_kernel<<<N, 256, SP_TOTAL>>>(E, spans, out);
}

// round 9
// speedup vs baseline: 2.7103x; 1.0928x over previous
#include <cuda_runtime.h>
#include <cuda_bf16.h>
#include <math.h>
#include <stdint.h>

#define D_DIM 768
#define T_MAX 8192
#define NT 256

// Scratch (__device__ globals per harness rules)
__device__ __nv_bfloat16 g_Qhi[(size_t)T_MAX * D_DIM];
__device__ __nv_bfloat16 g_Qlo[(size_t)T_MAX * D_DIM];
__device__ __nv_bfloat16 g_Ehi[(size_t)T_MAX * D_DIM];
__device__ __nv_bfloat16 g_Elo[(size_t)T_MAX * D_DIM];
__device__ __nv_bfloat16 g_Whi[(size_t)D_DIM * D_DIM];
__device__ __nv_bfloat16 g_Wlo[(size_t)D_DIM * D_DIM];

// ---------------------------------------------------------------------------
// Helpers (baseline PTX only — plain sm_103 target)
// ---------------------------------------------------------------------------
__device__ __forceinline__ uint32_t smem_u32(const void* p) {
    uint32_t a;
    asm("{ .reg .u64 t; cvta.to.shared.u64 t, %1; cvt.u32.u64 %0, t; }"
        : "=r"(a) : "l"(p));
    return a;
}
__device__ __forceinline__ void ldmx4(uint32_t* r, uint32_t addr) {
    asm volatile("ldmatrix.sync.aligned.m8n8.x4.shared.b16 {%0,%1,%2,%3}, [%4];"
                 : "=r"(r[0]), "=r"(r[1]), "=r"(r[2]), "=r"(r[3]) : "r"(addr));
}
__device__ __forceinline__ void mma16816(float* c, const uint32_t* a,
                                         const uint32_t* b) {
    asm volatile(
        "mma.sync.aligned.m16n8k16.row.col.f32.bf16.bf16.f32 "
        "{%0,%1,%2,%3}, {%4,%5,%6,%7}, {%8,%9}, {%0,%1,%2,%3};"
        : "+f"(c[0]), "+f"(c[1]), "+f"(c[2]), "+f"(c[3])
        : "r"(a[0]), "r"(a[1]), "r"(a[2]), "r"(a[3]), "r"(b[0]), "r"(b[1]));
}
__device__ __forceinline__ void cp16(uint32_t dst, const void* src) {
    asm volatile("cp.async.cg.shared.global [%0], [%1], 16;"
                 :: "r"(dst), "l"(src) : "memory");
}
#define CP_COMMIT() asm volatile("cp.async.commit_group;" ::: "memory")
#define CP_WAIT0()  asm volatile("cp.async.wait_group 0;" ::: "memory")
#define CP_WAIT1()  asm volatile("cp.async.wait_group 1;" ::: "memory")

// ---------------------------------------------------------------------------
// Kernel 0: fp32 -> (bf16 hi, bf16 lo) split
// ---------------------------------------------------------------------------
__global__ __launch_bounds__(256) void cvt_kernel(
    const float* __restrict__ src, __nv_bfloat16* __restrict__ hi,
    __nv_bfloat16* __restrict__ lo, int n4)
{
    int i = blockIdx.x * blockDim.x + threadIdx.x;
    if (i >= n4) return;
    float4 v = reinterpret_cast<const float4*>(src)[i];
    __nv_bfloat16 h0 = __float2bfloat16_rn(v.x);
    __nv_bfloat16 h1 = __float2bfloat16_rn(v.y);
    __nv_bfloat16 h2 = __float2bfloat16_rn(v.z);
    __nv_bfloat16 h3 = __float2bfloat16_rn(v.w);
    __nv_bfloat162* hp = reinterpret_cast<__nv_bfloat162*>(hi) + i * 2;
    __nv_bfloat162* lp = reinterpret_cast<__nv_bfloat162*>(lo) + i * 2;
    hp[0] = __nv_bfloat162(h0, h1);
    hp[1] = __nv_bfloat162(h2, h3);
    lp[0] = __nv_bfloat162(__float2bfloat16_rn(v.x - __bfloat162float(h0)),
                           __float2bfloat16_rn(v.y - __bfloat162float(h1)));
    lp[1] = __nv_bfloat162(__float2bfloat16_rn(v.z - __bfloat162float(h2)),
                           __float2bfloat16_rn(v.w - __bfloat162float(h3)));
}

// ---------------------------------------------------------------------------
// Kernel 1: Q = E @ Wq^T + bq (HMMA, bf16-split 3-MMA), cp.async 2-stage
// pipeline. CTA tile 128x128, BK=32, 8 warps (2x4).
// ---------------------------------------------------------------------------
#define PIT 80
#define SA_HI 0
#define SA_LO 10240
#define SB_HI 20480
#define SB_LO 30720
#define QS_STAGE 40960
#define QS_TOTAL 81920

__global__ __launch_bounds__(256, 2) void qproj_hmma_kernel(
    const __nv_bfloat16* __restrict__ Ehi, const __nv_bfloat16* __restrict__ Elo,
    const __nv_bfloat16* __restrict__ Whi, const __nv_bfloat16* __restrict__ Wlo,
    const float* __restrict__ bq, int T)
{
    extern __shared__ __align__(16) char qsm[];
    const uint32_t sb = smem_u32(qsm);
    const int tid = threadIdx.x;
    const int wid = tid >> 5, lane = tid & 31;
    const int wm = wid & 1, wn = wid >> 1;
    const int mbase = blockIdx.y * 128;
    const int nbase = blockIdx.x * 128;

    float acc[4][4][4];
#pragma unroll
    for (int mi = 0; mi < 4; mi++)
#pragma unroll
        for (int ni = 0; ni < 4; ni++)
#pragma unroll
            for (int q = 0; q < 4; q++) acc[mi][ni][q] = 0.f;

    const uint32_t a_lane = (uint32_t)((wm * 64 + (lane & 15)) * PIT + (lane >> 4) * 16);
    const uint32_t b_lane = (uint32_t)((wn * 32 + (lane & 7) + ((lane >> 4) << 3)) * PIT +
                                       ((lane >> 3) & 1) * 16);

    auto stage_chunk = [&](int c) {
        const int k0 = c * 32;
        const uint32_t db = sb + (uint32_t)(c & 1) * QS_STAGE;
#pragma unroll
        for (int i = 0; i < 2; i++) {
            int idx = i * 256 + tid;
            int r = idx >> 2, c4 = idx & 3;
            int ar = mbase + r; if (ar >= T) ar = T - 1;
            size_t ga = (size_t)ar * D_DIM + k0 + c4 * 8;
            size_t gb = (size_t)(nbase + r) * D_DIM + k0 + c4 * 8;
            uint32_t so = (uint32_t)(r * PIT + c4 * 16);
            cp16(db + SA_HI + so, Ehi + ga);
            cp16(db + SA_LO + so, Elo + ga);
            cp16(db + SB_HI + so, Whi + gb);
            cp16(db + SB_LO + so, Wlo + gb);
        }
    };

    stage_chunk(0);
    CP_COMMIT();

    const int NC = D_DIM / 32;    // 24
    for (int c = 0; c < NC; c++) {
        if (c + 1 < NC) { stage_chunk(c + 1); CP_COMMIT(); CP_WAIT1(); }
        else            { CP_WAIT0(); }
        __syncthreads();

        const uint32_t st = sb + (uint32_t)(c & 1) * QS_STAGE;
#pragma unroll
        for (int ks = 0; ks < 2; ks++) {
            const uint32_t ao = st + a_lane + ks * 32;
            const uint32_t bo = st + b_lane + ks * 32;
            uint32_t ah[4][4], al[4][4], bh[2][4], bl[2][4];
#pragma unroll
            for (int mi = 0; mi < 4; mi++) ldmx4(ah[mi], ao + SA_HI + mi * 16 * PIT);
#pragma unroll
            for (int np = 0; np < 2; np++) ldmx4(bh[np], bo + SB_HI + np * 16 * PIT);
#pragma unroll
            for (int mi = 0; mi < 4; mi++)
#pragma unroll
                for (int ni = 0; ni < 4; ni++)
                    mma16816(acc[mi][ni], ah[mi], &bh[ni >> 1][(ni & 1) * 2]);
#pragma unroll
            for (int np = 0; np < 2; np++) ldmx4(bl[np], bo + SB_LO + np * 16 * PIT);
#pragma unroll
            for (int mi = 0; mi < 4; mi++)
#pragma unroll
                for (int ni = 0; ni < 4; ni++)
                    mma16816(acc[mi][ni], ah[mi], &bl[ni >> 1][(ni & 1) * 2]);
#pragma unroll
            for (int mi = 0; mi < 4; mi++) ldmx4(al[mi], ao + SA_LO + mi * 16 * PIT);
#pragma unroll
            for (int mi = 0; mi < 4; mi++)
#pragma unroll
                for (int ni = 0; ni < 4; ni++)
                    mma16816(acc[mi][ni], al[mi], &bh[ni >> 1][(ni & 1) * 2]);
        }
        __syncthreads();
    }

    const int mrow0 = mbase + wm * 64 + (lane >> 2);
    const int ncol0 = nbase + wn * 32 + 2 * (lane & 3);
#pragma unroll
    for (int ni = 0; ni < 4; ni++) {
        int col = ncol0 + ni * 8;
        float2 bv = *reinterpret_cast<const float2*>(&bq[col]);
#pragma unroll
        for (int mi = 0; mi < 4; mi++) {
#pragma unroll
            for (int h = 0; h < 2; h++) {
                int r = mrow0 + mi * 16 + h * 8;
                if (r < T) {
                    float vx = acc[mi][ni][h * 2 + 0] + bv.x;
                    float vy = acc[mi][ni][h * 2 + 1] + bv.y;
                    __nv_bfloat16 hx = __float2bfloat16_rn(vx);
                    __nv_bfloat16 hy = __float2bfloat16_rn(vy);
                    size_t o = (size_t)r * D_DIM + col;
                    *reinterpret_cast<__nv_bfloat162*>(&g_Qhi[o]) = __nv_bfloat162(hx, hy);
                    *reinterpret_cast<__nv_bfloat162*>(&g_Qlo[o]) = __nv_bfloat162(
                        __float2bfloat16_rn(vx - __bfloat162float(hx)),
                        __float2bfloat16_rn(vy - __bfloat162float(hy)));
                }
            }
        }
    }
}

// ---------------------------------------------------------------------------
// Kernel 2: span attention, HMMA scores, 6 chunks of 128 dims, DOUBLE-BUFFERED
// cp.async pipeline (L2 latency hidden behind previous chunk's MMA).
// Smem layout (bytes):
//   buffer b (b=0,1) at b*34816:  4 arrays x (32 rows x 272 B) = 34816
//     array order: Qhi(0) Qlo(1) Ehi(2) Elo(3), each 8704 B
//   [69632, 73856)  S (32x33 f32)
//   [73856, 73984)  csum
//   warp partials (8 x 1056 f32 = 33792 B) reuse [0, 33792) after last MMA
// ---------------------------------------------------------------------------
#define SP_PIT   272
#define SP_ARR   8704
#define SP_BUF   34816
#define SP_S     69632
#define SP_CSUM  73856
#define SP_TOTAL 73984

template<int NBc>
__device__ __forceinline__ void span_scores_hmma(
    char* sm, uint32_t sb,
    const __nv_bfloat16* __restrict__ Qh, const __nv_bfloat16* __restrict__ Ql,
    const __nv_bfloat16* __restrict__ Eh, const __nv_bfloat16* __restrict__ El,
    int start, int tid)
{
    constexpr int MT = (NBc + 1) / 2;     // A m16-tiles
    constexpr int R8 = 8 * NBc;           // rows staged
    const int w = tid >> 5, lane = tid & 31;

    float acc[MT][NBc][4];
#pragma unroll
    for (int mi = 0; mi < MT; mi++)
#pragma unroll
        for (int ni = 0; ni < NBc; ni++)
#pragma unroll
            for (int q = 0; q < 4; q++) acc[mi][ni][q] = 0.f;

    const uint32_t a_lane = (uint32_t)((lane & 15) * SP_PIT + (lane >> 4) * 16);
    const uint32_t b_lane = (uint32_t)(((lane & 7) + ((lane >> 4) << 3)) * SP_PIT +
                                       ((lane >> 3) & 1) * 16);

    // stage chunk ch (dims [ch*128, ch*128+128)) into buffer ch&1
    auto stage = [&](int ch) {
        const uint32_t db = sb + (uint32_t)(ch & 1) * SP_BUF;
        const int koff = ch * 128;
#pragma unroll
        for (int i = 0; i < 2 * NBc; i++) {
            int idx = i * NT + tid;
            int a = idx / (R8 * 16);
            int rem = idx - a * (R8 * 16);
            int r = rem >> 4, c = rem & 15;
            const __nv_bfloat16* src = (a == 0) ? Qh : (a == 1) ? Ql :
                                       (a == 2) ? Eh : El;
            cp16(db + a * SP_ARR + r * SP_PIT + c * 16,
                 src + (size_t)(start + r) * D_DIM + koff + c * 8);
        }
    };

    stage(0);
    CP_COMMIT();

    for (int ch = 0; ch < 6; ch++) {
        if (ch < 5) { stage(ch + 1); CP_COMMIT(); CP_WAIT1(); }
        else        { CP_WAIT0(); }
        __syncthreads();

        // warp w owns k-dims [16w, 16w+16) of this chunk: one k-step
        const uint32_t st = sb + (uint32_t)(ch & 1) * SP_BUF;
        const uint32_t ao = st + a_lane + w * 32;
        const uint32_t bo = st + b_lane + w * 32;
        uint32_t ah[MT][4], al[MT][4], bh[MT][4], bl[MT][4];
#pragma unroll
        for (int mi = 0; mi < MT; mi++)
            ldmx4(ah[mi], ao + 0 * SP_ARR + mi * 16 * SP_PIT);
#pragma unroll
        for (int np = 0; np < MT; np++)
            ldmx4(bh[np], bo + 2 * SP_ARR + np * 16 * SP_PIT);
#pragma unroll
        for (int mi = 0; mi < MT; mi++)
#pragma unroll
            for (int ni = 0; ni < NBc; ni++)
                mma16816(acc[mi][ni], ah[mi], &bh[ni >> 1][(ni & 1) * 2]);
#pragma unroll
        for (int np = 0; np < MT; np++)
            ldmx4(bl[np], bo + 3 * SP_ARR + np * 16 * SP_PIT);
#pragma unroll
        for (int mi = 0; mi < MT; mi++)
#pragma unroll
            for (int ni = 0; ni < NBc; ni++)
                mma16816(acc[mi][ni], ah[mi], &bl[ni >> 1][(ni & 1) * 2]);
#pragma unroll
        for (int mi = 0; mi < MT; mi++)
            ldmx4(al[mi], ao + 1 * SP_ARR + mi * 16 * SP_PIT);
#pragma unroll
        for (int mi = 0; mi < MT; mi++)
#pragma unroll
            for (int ni = 0; ni < NBc; ni++)
                mma16816(acc[mi][ni], al[mi], &bh[ni >> 1][(ni & 1) * 2]);
        __syncthreads();
    }

    // ---- store warp partials into (reused) buffer region ----
    float* P = reinterpret_cast<float*>(sm) + w * 1056;
#pragma unroll
    for (int mi = 0; mi < MT; mi++)
#pragma unroll
        for (int ni = 0; ni < NBc; ni++) {
            int r0 = mi * 16 + (lane >> 2);
            int col = ni * 8 + 2 * (lane & 3);
            P[r0 * 33 + col]           = acc[mi][ni][0];
            P[r0 * 33 + col + 1]       = acc[mi][ni][1];
            P[(r0 + 8) * 33 + col]     = acc[mi][ni][2];
            P[(r0 + 8) * 33 + col + 1] = acc[mi][ni][3];
        }
}

__global__ __launch_bounds__(256, 3) void span_kernel(
    const float* __restrict__ E, const int* __restrict__ spans,
    float* __restrict__ out)
{
    extern __shared__ __align__(16) char sm[];
    const uint32_t sb = smem_u32(sm);
    float* S    = reinterpret_cast<float*>(sm + SP_S);
    float* csum = reinterpret_cast<float*>(sm + SP_CSUM);

    const int n = blockIdx.x;
    const int tid = threadIdx.x;
    const int start = spans[2 * n];
    const int len   = spans[2 * n + 1] - start + 1;   // 1..32
    const int nbc   = (len + 7) >> 3;                 // 1..4

    switch (nbc) {
        case 1: span_scores_hmma<1>(sm, sb, g_Qhi, g_Qlo, g_Ehi, g_Elo, start, tid); break;
        case 2: span_scores_hmma<2>(sm, sb, g_Qhi, g_Qlo, g_Ehi, g_Elo, start, tid); break;
        case 3: span_scores_hmma<3>(sm, sb, g_Qhi, g_Qlo, g_Ehi, g_Elo, start, tid); break;
        default: span_scores_hmma<4>(sm, sb, g_Qhi, g_Qlo, g_Ehi, g_Elo, start, tid); break;
    }
    __syncthreads();

    // ---- reduce 8 warp partials (len rows x side cols) ----
    const int side = nbc * 8;
    const float* P = reinterpret_cast<const float*>(sm);
    for (int idx = tid; idx < len * side; idx += NT) {
        int q = idx / side, k = idx - q * side;
        int o = q * 33 + k;
        float v = P[o];
#pragma unroll
        for (int w = 1; w < 8; w++) v += P[w * 1056 + o];
        S[o] = v;
    }
    __syncthreads();

    // ---- softmax over k (one warp per q-row) ----
    const int warp = tid >> 5, lane = tid & 31;
#pragma unroll
    for (int r = 0; r < 4; r++) {
        int q = warp + 8 * r;
        if (q < len) {
            float x = (lane < len) ? S[q * 33 + lane] : -INFINITY;
            float m = x;
#pragma unroll
            for (int off = 16; off; off >>= 1)
                m = fmaxf(m, __shfl_xor_sync(0xffffffffu, m, off));
            float e = (lane < len) ? __expf(x - m) : 0.f;
            float ssum = e;
#pragma unroll
            for (int off = 16; off; off >>= 1)
                ssum += __shfl_xor_sync(0xffffffffu, ssum, off);
            S[q * 33 + lane] = e / ssum;
        }
    }
    __syncthreads();

    // ---- column sums over valid q ----
    if (tid < 32) {
        float c = 0.f;
        if (tid < len)
            for (int q = 0; q < len; q++) c += S[q * 33 + tid];
        csum[tid] = c;
    }
    __syncthreads();

    // ---- out[n, d] = sum_k csum[k] * E[start + k, d]  (E fp32 via L2) ----
    {
        const float* eb = E + (size_t)start * D_DIM + tid;
        float a0 = 0.f, a1 = 0.f, a2 = 0.f;
        for (int k = 0; k < len; k++) {
            float w = csum[k];
            const float* p = eb + (size_t)k * D_DIM;
            a0 += w * p[0];
            a1 += w * p[256];
            a2 += w * p[512];
        }
        float* op = out + (size_t)n * D_DIM + tid;
        op[0]   = a0;
        op[256] = a1;
        op[512] = a2;
    }
}

// ---------------------------------------------------------------------------
// Launch
// ---------------------------------------------------------------------------
extern "C" void kernel_launch(void* const* d_in, const int* in_sizes, int n_in,
                              void* d_out, int out_size)
{
    const float* E     = (const float*)d_in[0];
    const int*   spans = (const int*)d_in[1];
    const float* Wq    = (const float*)d_in[2];
    const float* bq    = (const float*)d_in[3];
    float*       out   = (float*)d_out;

    const int T = in_sizes[0] / D_DIM;
    const int N = in_sizes[1] / 2;

    __nv_bfloat16 *eh, *el, *wh, *wl;
    cudaGetSymbolAddress((void**)&eh, g_Ehi);
    cudaGetSymbolAddress((void**)&el, g_Elo);
    cudaGetSymbolAddress((void**)&wh, g_Whi);
    cudaGetSymbolAddress((void**)&wl, g_Wlo);

    {
        int n4 = T * D_DIM / 4;
        cvt_kernel<<<(n4 + 255) / 256, 256>>>(E, eh, el, n4);
        int w4 = D_DIM * D_DIM / 4;
        cvt_kernel<<<(w4 + 255) / 256, 256>>>(Wq, wh, wl, w4);
    }

    {
        cudaFuncSetAttribute(qproj_hmma_kernel,
                             cudaFuncAttributeMaxDynamicSharedMemorySize, QS_TOTAL);
        dim3 gg(D_DIM / 128, (T + 127) / 128);
        qproj_hmma_kernel<<<gg, 256, QS_TOTAL>>>(eh, el, wh, wl, bq, T);
    }

    cudaFuncSetAttribute(span_kernel,
                         cudaFuncAttributeMaxDynamicSharedMemorySize, SP_TOTAL);
    span_kernel<<<N, 256, SP_TOTAL>>>(E, spans, out);
}

// round 10
// speedup vs baseline: 2.7587x; 1.0178x over previous
#include <cuda_runtime.h>
#include <cuda_bf16.h>
#include <math.h>
#include <stdint.h>

#define D_DIM 768
#define T_MAX 8192
#define NT 256

// Scratch (__device__ globals per harness rules)
__device__ __nv_bfloat16 g_Qhi[(size_t)T_MAX * D_DIM];
__device__ __nv_bfloat16 g_Qlo[(size_t)T_MAX * D_DIM];
__device__ __nv_bfloat16 g_Ehi[(size_t)T_MAX * D_DIM];
__device__ __nv_bfloat16 g_Elo[(size_t)T_MAX * D_DIM];
__device__ __nv_bfloat16 g_Whi[(size_t)D_DIM * D_DIM];
__device__ __nv_bfloat16 g_Wlo[(size_t)D_DIM * D_DIM];

// ---------------------------------------------------------------------------
// Helpers (baseline PTX only — plain sm_103 target)
// ---------------------------------------------------------------------------
__device__ __forceinline__ uint32_t smem_u32(const void* p) {
    uint32_t a;
    asm("{ .reg .u64 t; cvta.to.shared.u64 t, %1; cvt.u32.u64 %0, t; }"
        : "=r"(a) : "l"(p));
    return a;
}
__device__ __forceinline__ void ldmx4(uint32_t* r, uint32_t addr) {
    asm volatile("ldmatrix.sync.aligned.m8n8.x4.shared.b16 {%0,%1,%2,%3}, [%4];"
                 : "=r"(r[0]), "=r"(r[1]), "=r"(r[2]), "=r"(r[3]) : "r"(addr));
}
__device__ __forceinline__ void mma16816(float* c, const uint32_t* a,
                                         const uint32_t* b) {
    asm volatile(
        "mma.sync.aligned.m16n8k16.row.col.f32.bf16.bf16.f32 "
        "{%0,%1,%2,%3}, {%4,%5,%6,%7}, {%8,%9}, {%0,%1,%2,%3};"
        : "+f"(c[0]), "+f"(c[1]), "+f"(c[2]), "+f"(c[3])
        : "r"(a[0]), "r"(a[1]), "r"(a[2]), "r"(a[3]), "r"(b[0]), "r"(b[1]));
}
__device__ __forceinline__ void cp16(uint32_t dst, const void* src) {
    asm volatile("cp.async.cg.shared.global [%0], [%1], 16;"
                 :: "r"(dst), "l"(src) : "memory");
}
#define CP_COMMIT() asm volatile("cp.async.commit_group;" ::: "memory")
#define CP_WAIT0()  asm volatile("cp.async.wait_group 0;" ::: "memory")

// ---------------------------------------------------------------------------
// Kernel 0: fp32 -> (bf16 hi, bf16 lo) split
// ---------------------------------------------------------------------------
__global__ __launch_bounds__(256) void cvt_kernel(
    const float* __restrict__ src, __nv_bfloat16* __restrict__ hi,
    __nv_bfloat16* __restrict__ lo, int n4)
{
    int i = blockIdx.x * blockDim.x + threadIdx.x;
    if (i >= n4) return;
    float4 v = reinterpret_cast<const float4*>(src)[i];
    __nv_bfloat16 h0 = __float2bfloat16_rn(v.x);
    __nv_bfloat16 h1 = __float2bfloat16_rn(v.y);
    __nv_bfloat16 h2 = __float2bfloat16_rn(v.z);
    __nv_bfloat16 h3 = __float2bfloat16_rn(v.w);
    __nv_bfloat162* hp = reinterpret_cast<__nv_bfloat162*>(hi) + i * 2;
    __nv_bfloat162* lp = reinterpret_cast<__nv_bfloat162*>(lo) + i * 2;
    hp[0] = __nv_bfloat162(h0, h1);
    hp[1] = __nv_bfloat162(h2, h3);
    lp[0] = __nv_bfloat162(__float2bfloat16_rn(v.x - __bfloat162float(h0)),
                           __float2bfloat16_rn(v.y - __bfloat162float(h1)));
    lp[1] = __nv_bfloat162(__float2bfloat16_rn(v.z - __bfloat162float(h2)),
                           __float2bfloat16_rn(v.w - __bfloat162float(h3)));
}

// ---------------------------------------------------------------------------
// Kernel 1: Q = E @ Wq^T + bq (HMMA, bf16-split 3-MMA), cp.async 2-stage
// pipeline, ONE barrier per chunk. CTA tile 128x128, BK=32, 8 warps (2x4).
// ---------------------------------------------------------------------------
#define PIT 80
#define SA_HI 0
#define SA_LO 10240
#define SB_HI 20480
#define SB_LO 30720
#define QS_STAGE 40960
#define QS_TOTAL 81920

__global__ __launch_bounds__(256, 2) void qproj_hmma_kernel(
    const __nv_bfloat16* __restrict__ Ehi, const __nv_bfloat16* __restrict__ Elo,
    const __nv_bfloat16* __restrict__ Whi, const __nv_bfloat16* __restrict__ Wlo,
    const float* __restrict__ bq, int T)
{
    extern __shared__ __align__(16) char qsm[];
    const uint32_t sb = smem_u32(qsm);
    const int tid = threadIdx.x;
    const int wid = tid >> 5, lane = tid & 31;
    const int wm = wid & 1, wn = wid >> 1;
    const int mbase = blockIdx.y * 128;
    const int nbase = blockIdx.x * 128;

    float acc[4][4][4];
#pragma unroll
    for (int mi = 0; mi < 4; mi++)
#pragma unroll
        for (int ni = 0; ni < 4; ni++)
#pragma unroll
            for (int q = 0; q < 4; q++) acc[mi][ni][q] = 0.f;

    const uint32_t a_lane = (uint32_t)((wm * 64 + (lane & 15)) * PIT + (lane >> 4) * 16);
    const uint32_t b_lane = (uint32_t)((wn * 32 + (lane & 7) + ((lane >> 4) << 3)) * PIT +
                                       ((lane >> 3) & 1) * 16);

    auto stage_chunk = [&](int c) {
        const int k0 = c * 32;
        const uint32_t db = sb + (uint32_t)(c & 1) * QS_STAGE;
#pragma unroll
        for (int i = 0; i < 2; i++) {
            int idx = i * 256 + tid;
            int r = idx >> 2, c4 = idx & 3;
            int ar = mbase + r; if (ar >= T) ar = T - 1;
            size_t ga = (size_t)ar * D_DIM + k0 + c4 * 8;
            size_t gb = (size_t)(nbase + r) * D_DIM + k0 + c4 * 8;
            uint32_t so = (uint32_t)(r * PIT + c4 * 16);
            cp16(db + SA_HI + so, Ehi + ga);
            cp16(db + SA_LO + so, Elo + ga);
            cp16(db + SB_HI + so, Whi + gb);
            cp16(db + SB_LO + so, Wlo + gb);
        }
    };

    stage_chunk(0);
    CP_COMMIT();

    const int NC = D_DIM / 32;    // 24
    for (int c = 0; c < NC; c++) {
        CP_WAIT0();               // only this thread's stage(c) outstanding
        __syncthreads();          // data visible + buf[(c+1)&1] free
        if (c + 1 < NC) { stage_chunk(c + 1); CP_COMMIT(); }

        const uint32_t st = sb + (uint32_t)(c & 1) * QS_STAGE;
#pragma unroll
        for (int ks = 0; ks < 2; ks++) {
            const uint32_t ao = st + a_lane + ks * 32;
            const uint32_t bo = st + b_lane + ks * 32;
            uint32_t ah[4][4], al[4][4], bh[2][4], bl[2][4];
#pragma unroll
            for (int mi = 0; mi < 4; mi++) ldmx4(ah[mi], ao + SA_HI + mi * 16 * PIT);
#pragma unroll
            for (int np = 0; np < 2; np++) ldmx4(bh[np], bo + SB_HI + np * 16 * PIT);
#pragma unroll
            for (int mi = 0; mi < 4; mi++)
#pragma unroll
                for (int ni = 0; ni < 4; ni++)
                    mma16816(acc[mi][ni], ah[mi], &bh[ni >> 1][(ni & 1) * 2]);
#pragma unroll
            for (int np = 0; np < 2; np++) ldmx4(bl[np], bo + SB_LO + np * 16 * PIT);
#pragma unroll
            for (int mi = 0; mi < 4; mi++)
#pragma unroll
                for (int ni = 0; ni < 4; ni++)
                    mma16816(acc[mi][ni], ah[mi], &bl[ni >> 1][(ni & 1) * 2]);
#pragma unroll
            for (int mi = 0; mi < 4; mi++) ldmx4(al[mi], ao + SA_LO + mi * 16 * PIT);
#pragma unroll
            for (int mi = 0; mi < 4; mi++)
#pragma unroll
                for (int ni = 0; ni < 4; ni++)
                    mma16816(acc[mi][ni], al[mi], &bh[ni >> 1][(ni & 1) * 2]);
        }
    }

    const int mrow0 = mbase + wm * 64 + (lane >> 2);
    const int ncol0 = nbase + wn * 32 + 2 * (lane & 3);
#pragma unroll
    for (int ni = 0; ni < 4; ni++) {
        int col = ncol0 + ni * 8;
        float2 bv = *reinterpret_cast<const float2*>(&bq[col]);
#pragma unroll
        for (int mi = 0; mi < 4; mi++) {
#pragma unroll
            for (int h = 0; h < 2; h++) {
                int r = mrow0 + mi * 16 + h * 8;
                if (r < T) {
                    float vx = acc[mi][ni][h * 2 + 0] + bv.x;
                    float vy = acc[mi][ni][h * 2 + 1] + bv.y;
                    __nv_bfloat16 hx = __float2bfloat16_rn(vx);
                    __nv_bfloat16 hy = __float2bfloat16_rn(vy);
                    size_t o = (size_t)r * D_DIM + col;
                    *reinterpret_cast<__nv_bfloat162*>(&g_Qhi[o]) = __nv_bfloat162(hx, hy);
                    *reinterpret_cast<__nv_bfloat162*>(&g_Qlo[o]) = __nv_bfloat162(
                        __float2bfloat16_rn(vx - __bfloat162float(hx)),
                        __float2bfloat16_rn(vy - __bfloat162float(hy)));
                }
            }
        }
    }
}

// ---------------------------------------------------------------------------
// Kernel 2: span attention, HMMA scores, 6 chunks x 128 dims, double-buffered
// cp.async, ONE barrier per chunk, float4 partial reduce.
// Smem layout (bytes):
//   buffer b (b=0,1) at b*34816: 4 arrays x (32 rows x 272 B); arrays:
//     Qhi(0) Qlo(1) Ehi(2) Elo(3), each 8704 B
//   [69632, 73856)  S (32x33 f32)
//   [73856, 73984)  csum
//   warp partials: 8 x (32 x 36 f32) = 36864 B, reuse [0, 36864) after a
//   barrier (overlaps buf1 head, hence the pre-store barrier)
// ---------------------------------------------------------------------------
#define SP_PIT   272
#define SP_ARR   8704
#define SP_BUF   34816
#define SP_S     69632
#define SP_CSUM  73856
#define SP_TOTAL 73984
#define PP       36           // partial pitch (floats), 16B-aligned rows
#define PWARP    (32 * PP)    // floats per warp partial tile

template<int NBc>
__device__ __forceinline__ void span_scores_hmma(
    char* sm, uint32_t sb,
    const __nv_bfloat16* __restrict__ Qh, const __nv_bfloat16* __restrict__ Ql,
    const __nv_bfloat16* __restrict__ Eh, const __nv_bfloat16* __restrict__ El,
    int start, int tid)
{
    constexpr int MT = (NBc + 1) / 2;
    constexpr int R8 = 8 * NBc;
    const int w = tid >> 5, lane = tid & 31;

    float acc[MT][NBc][4];
#pragma unroll
    for (int mi = 0; mi < MT; mi++)
#pragma unroll
        for (int ni = 0; ni < NBc; ni++)
#pragma unroll
            for (int q = 0; q < 4; q++) acc[mi][ni][q] = 0.f;

    const uint32_t a_lane = (uint32_t)((lane & 15) * SP_PIT + (lane >> 4) * 16);
    const uint32_t b_lane = (uint32_t)(((lane & 7) + ((lane >> 4) << 3)) * SP_PIT +
                                       ((lane >> 3) & 1) * 16);

    auto stage = [&](int ch) {
        const uint32_t db = sb + (uint32_t)(ch & 1) * SP_BUF;
        const int koff = ch * 128;
#pragma unroll
        for (int i = 0; i < 2 * NBc; i++) {
            int idx = i * NT + tid;
            int a = idx / (R8 * 16);
            int rem = idx - a * (R8 * 16);
            int r = rem >> 4, c = rem & 15;
            const __nv_bfloat16* src = (a == 0) ? Qh : (a == 1) ? Ql :
                                       (a == 2) ? Eh : El;
            cp16(db + a * SP_ARR + r * SP_PIT + c * 16,
                 src + (size_t)(start + r) * D_DIM + koff + c * 8);
        }
    };

    stage(0);
    CP_COMMIT();

    for (int ch = 0; ch < 6; ch++) {
        CP_WAIT0();
        __syncthreads();
        if (ch < 5) { stage(ch + 1); CP_COMMIT(); }

        const uint32_t st = sb + (uint32_t)(ch & 1) * SP_BUF;
        const uint32_t ao = st + a_lane + w * 32;
        const uint32_t bo = st + b_lane + w * 32;
        uint32_t ah[MT][4], al[MT][4], bh[MT][4], bl[MT][4];
#pragma unroll
        for (int mi = 0; mi < MT; mi++)
            ldmx4(ah[mi], ao + 0 * SP_ARR + mi * 16 * SP_PIT);
#pragma unroll
        for (int np = 0; np < MT; np++)
            ldmx4(bh[np], bo + 2 * SP_ARR + np * 16 * SP_PIT);
#pragma unroll
        for (int mi = 0; mi < MT; mi++)
#pragma unroll
            for (int ni = 0; ni < NBc; ni++)
                mma16816(acc[mi][ni], ah[mi], &bh[ni >> 1][(ni & 1) * 2]);
#pragma unroll
        for (int np = 0; np < MT; np++)
            ldmx4(bl[np], bo + 3 * SP_ARR + np * 16 * SP_PIT);
#pragma unroll
        for (int mi = 0; mi < MT; mi++)
#pragma unroll
            for (int ni = 0; ni < NBc; ni++)
                mma16816(acc[mi][ni], ah[mi], &bl[ni >> 1][(ni & 1) * 2]);
#pragma unroll
        for (int mi = 0; mi < MT; mi++)
            ldmx4(al[mi], ao + 1 * SP_ARR + mi * 16 * SP_PIT);
#pragma unroll
        for (int mi = 0; mi < MT; mi++)
#pragma unroll
            for (int ni = 0; ni < NBc; ni++)
                mma16816(acc[mi][ni], al[mi], &bh[ni >> 1][(ni & 1) * 2]);
    }

    __syncthreads();   // all warps done with buf1 before partials overwrite it

    float* P = reinterpret_cast<float*>(sm) + w * PWARP;
#pragma unroll
    for (int mi = 0; mi < MT; mi++)
#pragma unroll
        for (int ni = 0; ni < NBc; ni++) {
            int r0 = mi * 16 + (lane >> 2);
            int col = ni * 8 + 2 * (lane & 3);
            P[r0 * PP + col]           = acc[mi][ni][0];
            P[r0 * PP + col + 1]       = acc[mi][ni][1];
            P[(r0 + 8) * PP + col]     = acc[mi][ni][2];
            P[(r0 + 8) * PP + col + 1] = acc[mi][ni][3];
        }
}

__global__ __launch_bounds__(256, 3) void span_kernel(
    const float* __restrict__ E, const int* __restrict__ spans,
    float* __restrict__ out)
{
    extern __shared__ __align__(16) char sm[];
    const uint32_t sb = smem_u32(sm);
    float* S    = reinterpret_cast<float*>(sm + SP_S);
    float* csum = reinterpret_cast<float*>(sm + SP_CSUM);

    const int n = blockIdx.x;
    const int tid = threadIdx.x;
    const int start = spans[2 * n];
    const int len   = spans[2 * n + 1] - start + 1;   // 1..32
    const int nbc   = (len + 7) >> 3;                 // 1..4

    switch (nbc) {
        case 1: span_scores_hmma<1>(sm, sb, g_Qhi, g_Qlo, g_Ehi, g_Elo, start, tid); break;
        case 2: span_scores_hmma<2>(sm, sb, g_Qhi, g_Qlo, g_Ehi, g_Elo, start, tid); break;
        case 3: span_scores_hmma<3>(sm, sb, g_Qhi, g_Qlo, g_Ehi, g_Elo, start, tid); break;
        default: span_scores_hmma<4>(sm, sb, g_Qhi, g_Qlo, g_Ehi, g_Elo, start, tid); break;
    }
    __syncthreads();

    // ---- reduce 8 warp partials: float4 over len rows x side cols ----
    const int side = nbc * 8;
    const int s4 = side >> 2;
    const float* P = reinterpret_cast<const float*>(sm);
    for (int idx = tid; idx < len * s4; idx += NT) {
        int q = idx / s4, kq = idx - q * s4;
        const float* p0 = P + q * PP + kq * 4;
        float4 v = *reinterpret_cast<const float4*>(p0);
#pragma unroll
        for (int w = 1; w < 8; w++) {
            float4 t = *reinterpret_cast<const float4*>(p0 + w * PWARP);
            v.x += t.x; v.y += t.y; v.z += t.z; v.w += t.w;
        }
        float* d = S + q * 33 + kq * 4;
        d[0] = v.x; d[1] = v.y; d[2] = v.z; d[3] = v.w;
    }
    __syncthreads();

    // ---- softmax over k (one warp per q-row) ----
    const int warp = tid >> 5, lane = tid & 31;
#pragma unroll
    for (int r = 0; r < 4; r++) {
        int q = warp + 8 * r;
        if (q < len) {
            float x = (lane < len) ? S[q * 33 + lane] : -INFINITY;
            float m = x;
#pragma unroll
            for (int off = 16; off; off >>= 1)
                m = fmaxf(m, __shfl_xor_sync(0xffffffffu, m, off));
            float e = (lane < len) ? __expf(x - m) : 0.f;
            float ssum = e;
#pragma unroll
            for (int off = 16; off; off >>= 1)
                ssum += __shfl_xor_sync(0xffffffffu, ssum, off);
            S[q * 33 + lane] = e / ssum;
        }
    }
    __syncthreads();

    // ---- column sums over valid q ----
    if (tid < 32) {
        float c = 0.f;
        if (tid < len)
            for (int q = 0; q < len; q++) c += S[q * 33 + tid];
        csum[tid] = c;
    }
    __syncthreads();

    // ---- out[n, d] = sum_k csum[k] * E[start + k, d]  (E fp32 via L2) ----
    {
        const float* eb = E + (size_t)start * D_DIM + tid;
        float a0 = 0.f, a1 = 0.f, a2 = 0.f;
        for (int k = 0; k < len; k++) {
            float w = csum[k];
            const float* p = eb + (size_t)k * D_DIM;
            a0 += w * p[0];
            a1 += w * p[256];
            a2 += w * p[512];
        }
        float* op = out + (size_t)n * D_DIM + tid;
        op[0]   = a0;
        op[256] = a1;
        op[512] = a2;
    }
}

// ---------------------------------------------------------------------------
// Launch
// ---------------------------------------------------------------------------
extern "C" void kernel_launch(void* const* d_in, const int* in_sizes, int n_in,
                              void* d_out, int out_size)
{
    const float* E     = (const float*)d_in[0];
    const int*   spans = (const int*)d_in[1];
    const float* Wq    = (const float*)d_in[2];
    const float* bq    = (const float*)d_in[3];
    float*       out   = (float*)d_out;

    const int T = in_sizes[0] / D_DIM;
    const int N = in_sizes[1] / 2;

    __nv_bfloat16 *eh, *el, *wh, *wl;
    cudaGetSymbolAddress((void**)&eh, g_Ehi);
    cudaGetSymbolAddress((void**)&el, g_Elo);
    cudaGetSymbolAddress((void**)&wh, g_Whi);
    cudaGetSymbolAddress((void**)&wl, g_Wlo);

    {
        int n4 = T * D_DIM / 4;
        cvt_kernel<<<(n4 + 255) / 256, 256>>>(E, eh, el, n4);
        int w4 = D_DIM * D_DIM / 4;
        cvt_kernel<<<(w4 + 255) / 256, 256>>>(Wq, wh, wl, w4);
    }

    {
        cudaFuncSetAttribute(qproj_hmma_kernel,
                             cudaFuncAttributeMaxDynamicSharedMemorySize, QS_TOTAL);
        dim3 gg(D_DIM / 128, (T + 127) / 128);
        qproj_hmma_kernel<<<gg, 256, QS_TOTAL>>>(eh, el, wh, wl, bq, T);
    }

    cudaFuncSetAttribute(span_kernel,
                         cudaFuncAttributeMaxDynamicSharedMemorySize, SP_TOTAL);
    span_kernel<<<N, 256, SP_TOTAL>>>(E, spans, out);
}

// round 11
// speedup vs baseline: 4.7780x; 1.7320x over previous
#include <cuda_runtime.h>
#include <cuda_bf16.h>
#include <math.h>
#include <stdint.h>

#define D_DIM 768
#define T_MAX 8192
#define NT 256

// Scratch (__device__ globals per harness rules)
__device__ __nv_bfloat16 g_Qhi[(size_t)T_MAX * D_DIM];
__device__ __nv_bfloat16 g_Qlo[(size_t)T_MAX * D_DIM];
__device__ __nv_bfloat16 g_Ehi[(size_t)T_MAX * D_DIM];
__device__ __nv_bfloat16 g_Elo[(size_t)T_MAX * D_DIM];
__device__ __nv_bfloat16 g_Whi[(size_t)D_DIM * D_DIM];
__device__ __nv_bfloat16 g_Wlo[(size_t)D_DIM * D_DIM];
// Score band: Band[t][d+32] = Q[t] . E[t+d],  d in [-32, 32)
__device__ float g_Band[(size_t)T_MAX * 64];

// ---------------------------------------------------------------------------
// Helpers (baseline PTX only — plain sm_103 target)
// ---------------------------------------------------------------------------
__device__ __forceinline__ uint32_t smem_u32(const void* p) {
    uint32_t a;
    asm("{ .reg .u64 t; cvta.to.shared.u64 t, %1; cvt.u32.u64 %0, t; }"
        : "=r"(a) : "l"(p));
    return a;
}
__device__ __forceinline__ void ldmx4(uint32_t* r, uint32_t addr) {
    asm volatile("ldmatrix.sync.aligned.m8n8.x4.shared.b16 {%0,%1,%2,%3}, [%4];"
                 : "=r"(r[0]), "=r"(r[1]), "=r"(r[2]), "=r"(r[3]) : "r"(addr));
}
__device__ __forceinline__ void mma16816(float* c, const uint32_t* a,
                                         const uint32_t* b) {
    asm volatile(
        "mma.sync.aligned.m16n8k16.row.col.f32.bf16.bf16.f32 "
        "{%0,%1,%2,%3}, {%4,%5,%6,%7}, {%8,%9}, {%0,%1,%2,%3};"
        : "+f"(c[0]), "+f"(c[1]), "+f"(c[2]), "+f"(c[3])
        : "r"(a[0]), "r"(a[1]), "r"(a[2]), "r"(a[3]), "r"(b[0]), "r"(b[1]));
}
__device__ __forceinline__ void cp16(uint32_t dst, const void* src) {
    asm volatile("cp.async.cg.shared.global [%0], [%1], 16;"
                 :: "r"(dst), "l"(src) : "memory");
}
#define CP_COMMIT() asm volatile("cp.async.commit_group;" ::: "memory")
#define CP_WAIT0()  asm volatile("cp.async.wait_group 0;" ::: "memory")

// ---------------------------------------------------------------------------
// Kernel 0: fp32 -> (bf16 hi, bf16 lo) split
// ---------------------------------------------------------------------------
__global__ __launch_bounds__(256) void cvt_kernel(
    const float* __restrict__ src, __nv_bfloat16* __restrict__ hi,
    __nv_bfloat16* __restrict__ lo, int n4)
{
    int i = blockIdx.x * blockDim.x + threadIdx.x;
    if (i >= n4) return;
    float4 v = reinterpret_cast<const float4*>(src)[i];
    __nv_bfloat16 h0 = __float2bfloat16_rn(v.x);
    __nv_bfloat16 h1 = __float2bfloat16_rn(v.y);
    __nv_bfloat16 h2 = __float2bfloat16_rn(v.z);
    __nv_bfloat16 h3 = __float2bfloat16_rn(v.w);
    __nv_bfloat162* hp = reinterpret_cast<__nv_bfloat162*>(hi) + i * 2;
    __nv_bfloat162* lp = reinterpret_cast<__nv_bfloat162*>(lo) + i * 2;
    hp[0] = __nv_bfloat162(h0, h1);
    hp[1] = __nv_bfloat162(h2, h3);
    lp[0] = __nv_bfloat162(__float2bfloat16_rn(v.x - __bfloat162float(h0)),
                           __float2bfloat16_rn(v.y - __bfloat162float(h1)));
    lp[1] = __nv_bfloat162(__float2bfloat16_rn(v.z - __bfloat162float(h2)),
                           __float2bfloat16_rn(v.w - __bfloat162float(h3)));
}

// ---------------------------------------------------------------------------
// Kernel 1: Q = E @ Wq^T + bq (HMMA, bf16-split 3-MMA), cp.async 2-stage
// pipeline. CTA tile 128x128, BK=32, 8 warps (2x4). Writes Q as bf16 hi/lo.
// ---------------------------------------------------------------------------
#define PIT 80
#define SA_HI 0
#define SA_LO 10240
#define SB_HI 20480
#define SB_LO 30720
#define QS_STAGE 40960
#define QS_TOTAL 81920

__global__ __launch_bounds__(256, 2) void qproj_hmma_kernel(
    const __nv_bfloat16* __restrict__ Ehi, const __nv_bfloat16* __restrict__ Elo,
    const __nv_bfloat16* __restrict__ Whi, const __nv_bfloat16* __restrict__ Wlo,
    const float* __restrict__ bq, int T)
{
    extern __shared__ __align__(16) char qsm[];
    const uint32_t sb = smem_u32(qsm);
    const int tid = threadIdx.x;
    const int wid = tid >> 5, lane = tid & 31;
    const int wm = wid & 1, wn = wid >> 1;
    const int mbase = blockIdx.y * 128;
    const int nbase = blockIdx.x * 128;

    float acc[4][4][4];
#pragma unroll
    for (int mi = 0; mi < 4; mi++)
#pragma unroll
        for (int ni = 0; ni < 4; ni++)
#pragma unroll
            for (int q = 0; q < 4; q++) acc[mi][ni][q] = 0.f;

    const uint32_t a_lane = (uint32_t)((wm * 64 + (lane & 15)) * PIT + (lane >> 4) * 16);
    const uint32_t b_lane = (uint32_t)((wn * 32 + (lane & 7) + ((lane >> 4) << 3)) * PIT +
                                       ((lane >> 3) & 1) * 16);

    auto stage_chunk = [&](int c) {
        const int k0 = c * 32;
        const uint32_t db = sb + (uint32_t)(c & 1) * QS_STAGE;
#pragma unroll
        for (int i = 0; i < 2; i++) {
            int idx = i * 256 + tid;
            int r = idx >> 2, c4 = idx & 3;
            int ar = mbase + r; if (ar >= T) ar = T - 1;
            size_t ga = (size_t)ar * D_DIM + k0 + c4 * 8;
            size_t gb = (size_t)(nbase + r) * D_DIM + k0 + c4 * 8;
            uint32_t so = (uint32_t)(r * PIT + c4 * 16);
            cp16(db + SA_HI + so, Ehi + ga);
            cp16(db + SA_LO + so, Elo + ga);
            cp16(db + SB_HI + so, Whi + gb);
            cp16(db + SB_LO + so, Wlo + gb);
        }
    };

    stage_chunk(0);
    CP_COMMIT();

    const int NC = D_DIM / 32;    // 24
    for (int c = 0; c < NC; c++) {
        CP_WAIT0();
        __syncthreads();
        if (c + 1 < NC) { stage_chunk(c + 1); CP_COMMIT(); }

        const uint32_t st = sb + (uint32_t)(c & 1) * QS_STAGE;
#pragma unroll
        for (int ks = 0; ks < 2; ks++) {
            const uint32_t ao = st + a_lane + ks * 32;
            const uint32_t bo = st + b_lane + ks * 32;
            uint32_t ah[4][4], al[4][4], bh[2][4], bl[2][4];
#pragma unroll
            for (int mi = 0; mi < 4; mi++) ldmx4(ah[mi], ao + SA_HI + mi * 16 * PIT);
#pragma unroll
            for (int np = 0; np < 2; np++) ldmx4(bh[np], bo + SB_HI + np * 16 * PIT);
#pragma unroll
            for (int mi = 0; mi < 4; mi++)
#pragma unroll
                for (int ni = 0; ni < 4; ni++)
                    mma16816(acc[mi][ni], ah[mi], &bh[ni >> 1][(ni & 1) * 2]);
#pragma unroll
            for (int np = 0; np < 2; np++) ldmx4(bl[np], bo + SB_LO + np * 16 * PIT);
#pragma unroll
            for (int mi = 0; mi < 4; mi++)
#pragma unroll
                for (int ni = 0; ni < 4; ni++)
                    mma16816(acc[mi][ni], ah[mi], &bl[ni >> 1][(ni & 1) * 2]);
#pragma unroll
            for (int mi = 0; mi < 4; mi++) ldmx4(al[mi], ao + SA_LO + mi * 16 * PIT);
#pragma unroll
            for (int mi = 0; mi < 4; mi++)
#pragma unroll
                for (int ni = 0; ni < 4; ni++)
                    mma16816(acc[mi][ni], al[mi], &bh[ni >> 1][(ni & 1) * 2]);
        }
    }

    const int mrow0 = mbase + wm * 64 + (lane >> 2);
    const int ncol0 = nbase + wn * 32 + 2 * (lane & 3);
#pragma unroll
    for (int ni = 0; ni < 4; ni++) {
        int col = ncol0 + ni * 8;
        float2 bv = *reinterpret_cast<const float2*>(&bq[col]);
#pragma unroll
        for (int mi = 0; mi < 4; mi++) {
#pragma unroll
            for (int h = 0; h < 2; h++) {
                int r = mrow0 + mi * 16 + h * 8;
                if (r < T) {
                    float vx = acc[mi][ni][h * 2 + 0] + bv.x;
                    float vy = acc[mi][ni][h * 2 + 1] + bv.y;
                    __nv_bfloat16 hx = __float2bfloat16_rn(vx);
                    __nv_bfloat16 hy = __float2bfloat16_rn(vy);
                    size_t o = (size_t)r * D_DIM + col;
                    *reinterpret_cast<__nv_bfloat162*>(&g_Qhi[o]) = __nv_bfloat162(hx, hy);
                    *reinterpret_cast<__nv_bfloat162*>(&g_Qlo[o]) = __nv_bfloat162(
                        __float2bfloat16_rn(vx - __bfloat162float(hx)),
                        __float2bfloat16_rn(vy - __bfloat162float(hy)));
                }
            }
        }
    }
}

// ---------------------------------------------------------------------------
// Kernel 1b: score band.  Band[t][d+32] = Q[t] . E[t+d],  d in [-32, 32).
// Per CTA: GEMM tile M=32 (Q rows t0..t0+31) x N=128 (E rows t0-32..t0+95),
// K=768, bf16-split 3-MMA, cp.async double-buffered, BK=32.
// 8 warps: wm = wid&1 (m16), wn = wid>>1 (n32).
// ---------------------------------------------------------------------------
#define BQ_HI 0
#define BQ_LO 2560
#define BE_HI 5120
#define BE_LO 15360
#define B_STAGE 25600
#define B_TOTAL 51200

__global__ __launch_bounds__(256, 2) void band_kernel(
    const __nv_bfloat16* __restrict__ Qh, const __nv_bfloat16* __restrict__ Ql,
    const __nv_bfloat16* __restrict__ Eh, const __nv_bfloat16* __restrict__ El,
    int T)
{
    extern __shared__ __align__(16) char bsm[];
    const uint32_t sb = smem_u32(bsm);
    const int tid = threadIdx.x;
    const int wid = tid >> 5, lane = tid & 31;
    const int wm = wid & 1, wn = wid >> 1;
    const int t0 = blockIdx.x * 32;

    float acc[4][4];
#pragma unroll
    for (int ni = 0; ni < 4; ni++)
#pragma unroll
        for (int q = 0; q < 4; q++) acc[ni][q] = 0.f;

    const uint32_t a_lane = (uint32_t)((wm * 16 + (lane & 15)) * PIT + (lane >> 4) * 16);
    const uint32_t b_lane = (uint32_t)((wn * 32 + (lane & 7) + ((lane >> 4) << 3)) * PIT +
                                       ((lane >> 3) & 1) * 16);

    auto stage_chunk = [&](int c) {
        const int k0 = c * 32;
        const uint32_t db = sb + (uint32_t)(c & 1) * B_STAGE;
        // 320 rows total: Qhi[0,32) Qlo[32,64) Ehi[64,192) Elo[192,320)
#pragma unroll
        for (int i = 0; i < 5; i++) {
            int idx = i * 256 + tid;
            int row = idx >> 2, c4 = idx & 3;
            uint32_t base;
            const __nv_bfloat16* src;
            int g;
            if (row < 64) {
                int r = row & 31;
                base = (row < 32) ? BQ_HI : BQ_LO;
                src  = (row < 32) ? Qh : Ql;
                g = t0 + r;
                if (g >= T) g = T - 1;
                base += (uint32_t)(r * PIT);
            } else {
                int r = (row - 64) & 127;
                base = (row < 192) ? BE_HI : BE_LO;
                src  = (row < 192) ? Eh : El;
                g = t0 - 32 + r;
                if (g < 0) g = 0;
                if (g >= T) g = T - 1;
                base += (uint32_t)(r * PIT);
            }
            cp16(db + base + c4 * 16, src + (size_t)g * D_DIM + k0 + c4 * 8);
        }
    };

    stage_chunk(0);
    CP_COMMIT();

    const int NC = D_DIM / 32;    // 24
    for (int c = 0; c < NC; c++) {
        CP_WAIT0();
        __syncthreads();
        if (c + 1 < NC) { stage_chunk(c + 1); CP_COMMIT(); }

        const uint32_t st = sb + (uint32_t)(c & 1) * B_STAGE;
#pragma unroll
        for (int ks = 0; ks < 2; ks++) {
            const uint32_t ao = st + a_lane + ks * 32;
            const uint32_t bo = st + b_lane + ks * 32;
            uint32_t ah[4], al[4], bh[2][4], bl[2][4];
            ldmx4(ah, ao + BQ_HI);
#pragma unroll
            for (int np = 0; np < 2; np++) ldmx4(bh[np], bo + BE_HI + np * 16 * PIT);
#pragma unroll
            for (int ni = 0; ni < 4; ni++)
                mma16816(acc[ni], ah, &bh[ni >> 1][(ni & 1) * 2]);
#pragma unroll
            for (int np = 0; np < 2; np++) ldmx4(bl[np], bo + BE_LO + np * 16 * PIT);
#pragma unroll
            for (int ni = 0; ni < 4; ni++)
                mma16816(acc[ni], ah, &bl[ni >> 1][(ni & 1) * 2]);
            ldmx4(al, ao + BQ_LO);
#pragma unroll
            for (int ni = 0; ni < 4; ni++)
                mma16816(acc[ni], al, &bh[ni >> 1][(ni & 1) * 2]);
        }
    }

    // Epilogue: value at (r, c) = Q[t0+r] . E[t0-32+c]; band col = c - r.
    const int r_base = wm * 16 + (lane >> 2);
    const int c_base = wn * 32 + 2 * (lane & 3);
#pragma unroll
    for (int ni = 0; ni < 4; ni++) {
        int c = c_base + ni * 8;
#pragma unroll
        for (int h = 0; h < 2; h++) {
            int r = r_base + h * 8;
            int t = t0 + r;
            if (t < T) {
                int cc0 = c - r;
                if (cc0 >= 0 && cc0 < 64)
                    g_Band[(size_t)t * 64 + cc0] = acc[ni][h * 2 + 0];
                int cc1 = cc0 + 1;
                if (cc1 >= 0 && cc1 < 64)
                    g_Band[(size_t)t * 64 + cc1] = acc[ni][h * 2 + 1];
            }
        }
    }
}

// ---------------------------------------------------------------------------
// Kernel 2: span attention — reads precomputed band, softmax, csum, epilogue.
// No Q/E staging; tiny smem -> high occupancy.
// ---------------------------------------------------------------------------
__global__ __launch_bounds__(256) void span_kernel(
    const float* __restrict__ E, const int* __restrict__ spans,
    float* __restrict__ out)
{
    __shared__ float S[32 * 33];
    __shared__ float csum[32];

    const int n = blockIdx.x;
    const int tid = threadIdx.x;
    const int start = spans[2 * n];
    const int len   = spans[2 * n + 1] - start + 1;   // 1..32

    const int warp = tid >> 5, lane = tid & 31;

    // ---- softmax over k, reading scores straight from the band ----
#pragma unroll
    for (int r = 0; r < 4; r++) {
        int q = warp + 8 * r;
        if (q < len) {
            float x = (lane < len)
                ? g_Band[(size_t)(start + q) * 64 + (lane - q + 32)]
                : -INFINITY;
            float m = x;
#pragma unroll
            for (int off = 16; off; off >>= 1)
                m = fmaxf(m, __shfl_xor_sync(0xffffffffu, m, off));
            float e = (lane < len) ? __expf(x - m) : 0.f;
            float ssum = e;
#pragma unroll
            for (int off = 16; off; off >>= 1)
                ssum += __shfl_xor_sync(0xffffffffu, ssum, off);
            S[q * 33 + lane] = e / ssum;
        }
    }
    __syncthreads();

    // ---- column sums over valid q ----
    if (tid < 32) {
        float c = 0.f;
        if (tid < len)
            for (int q = 0; q < len; q++) c += S[q * 33 + tid];
        csum[tid] = c;
    }
    __syncthreads();

    // ---- out[n, d] = sum_k csum[k] * E[start + k, d]  (E fp32 via L2) ----
    {
        const float* eb = E + (size_t)start * D_DIM + tid;
        float a0 = 0.f, a1 = 0.f, a2 = 0.f;
        for (int k = 0; k < len; k++) {
            float w = csum[k];
            const float* p = eb + (size_t)k * D_DIM;
            a0 += w * p[0];
            a1 += w * p[256];
            a2 += w * p[512];
        }
        float* op = out + (size_t)n * D_DIM + tid;
        op[0]   = a0;
        op[256] = a1;
        op[512] = a2;
    }
}

// ---------------------------------------------------------------------------
// Launch
// ---------------------------------------------------------------------------
extern "C" void kernel_launch(void* const* d_in, const int* in_sizes, int n_in,
                              void* d_out, int out_size)
{
    const float* E     = (const float*)d_in[0];
    const int*   spans = (const int*)d_in[1];
    const float* Wq    = (const float*)d_in[2];
    const float* bq    = (const float*)d_in[3];
    float*       out   = (float*)d_out;

    const int T = in_sizes[0] / D_DIM;
    const int N = in_sizes[1] / 2;

    __nv_bfloat16 *eh, *el, *wh, *wl, *qh, *ql;
    cudaGetSymbolAddress((void**)&eh, g_Ehi);
    cudaGetSymbolAddress((void**)&el, g_Elo);
    cudaGetSymbolAddress((void**)&wh, g_Whi);
    cudaGetSymbolAddress((void**)&wl, g_Wlo);
    cudaGetSymbolAddress((void**)&qh, g_Qhi);
    cudaGetSymbolAddress((void**)&ql, g_Qlo);

    {
        int n4 = T * D_DIM / 4;
        cvt_kernel<<<(n4 + 255) / 256, 256>>>(E, eh, el, n4);
        int w4 = D_DIM * D_DIM / 4;
        cvt_kernel<<<(w4 + 255) / 256, 256>>>(Wq, wh, wl, w4);
    }

    {
        cudaFuncSetAttribute(qproj_hmma_kernel,
                             cudaFuncAttributeMaxDynamicSharedMemorySize, QS_TOTAL);
        dim3 gg(D_DIM / 128, (T + 127) / 128);
        qproj_hmma_kernel<<<gg, 256, QS_TOTAL>>>(eh, el, wh, wl, bq, T);
    }

    {
        cudaFuncSetAttribute(band_kernel,
                             cudaFuncAttributeMaxDynamicSharedMemorySize, B_TOTAL);
        band_kernel<<<(T + 31) / 32, 256, B_TOTAL>>>(qh, ql, eh, el, T);
    }

    span_kernel<<<N, 256>>>(E, spans, out);
}